// round 4
// baseline (speedup 1.0000x reference)
#include <cuda_runtime.h>

#define DK 128
#define BB 128
#define SS 128
#define NQ 101
#define NROWS 104   // 101 rows padded to 8*13

// ---------------- device-global scratch (no runtime allocation) ----------------
__device__ float g_AL[BB * SS * DK];   // all_learning
__device__ float g_P2[BB * SS * DK];   // precomputed z@W2 (non-recurrent part) + b2
__device__ float g_P3[BB * SS * DK];
__device__ float g_P4[BB * SS * DK];   // it@W4c^T + b4
__device__ float g_P5[BB * SS * DK];   // e_next@W5a^T + b5
__device__ float g_WT[15 * DK * DK];   // transposed 128x128 weight slices [k][d]
__device__ float g_r1[DK];             // rowsum of W1[:,256:384]

// WT slice ids
#define W1aT 0
#define W1bT 1
#define W2aT 2
#define W2bT 3
#define W2cT 4
#define W2dT 5
#define W3aT 6
#define W3bT 7
#define W3cT 8
#define W3dT 9
#define W4aT 10
#define W4bT 11
#define W4cT 12
#define W5aT 13
#define W5bT 14

__device__ __forceinline__ float sigmoidf(float x) { return 1.0f / (1.0f + __expf(-x)); }

// ---------------- transpose kernel: build WT slices + r1 ----------------
__global__ void k_transpose(const float* __restrict__ W1, const float* __restrict__ W2,
                            const float* __restrict__ W3, const float* __restrict__ W4,
                            const float* __restrict__ W5) {
    int m = blockIdx.x;
    const float* src; int ld, off;
    switch (m) {
        case 0:  src = W1; ld = 384; off = 0;   break;
        case 1:  src = W1; ld = 384; off = 128; break;
        case 2:  src = W2; ld = 512; off = 0;   break;
        case 3:  src = W2; ld = 512; off = 128; break;
        case 4:  src = W2; ld = 512; off = 256; break;
        case 5:  src = W2; ld = 512; off = 384; break;
        case 6:  src = W3; ld = 512; off = 0;   break;
        case 7:  src = W3; ld = 512; off = 128; break;
        case 8:  src = W3; ld = 512; off = 256; break;
        case 9:  src = W3; ld = 512; off = 384; break;
        case 10: src = W4; ld = 384; off = 0;   break;
        case 11: src = W4; ld = 384; off = 128; break;
        case 12: src = W4; ld = 384; off = 256; break;
        case 13: src = W5; ld = 256; off = 0;   break;
        default: src = W5; ld = 256; off = 128; break;
    }
    float* dst = g_WT + m * DK * DK;
    for (int idx = threadIdx.x; idx < DK * DK; idx += blockDim.x) {
        int d = idx >> 7, k = idx & 127;
        dst[k * DK + d] = src[d * ld + off + k];
    }
    if (m == 0) {
        for (int d = threadIdx.x; d < DK; d += blockDim.x) {
            float s = 0.f;
            for (int j = 0; j < 128; j++) s += W1[d * 384 + 256 + j];
            g_r1[d] = s;
        }
    }
}

// ---------------- GEMM helpers (8t x 8d register blocking, k=128) ----------------
__device__ __forceinline__ void acc_init(float acc[8][8], const float* __restrict__ bias, int d0) {
    float4 b0 = *(const float4*)(bias + d0);
    float4 b1 = *(const float4*)(bias + d0 + 4);
#pragma unroll
    for (int i = 0; i < 8; i++) {
        acc[i][0] = b0.x; acc[i][1] = b0.y; acc[i][2] = b0.z; acc[i][3] = b0.w;
        acc[i][4] = b1.x; acc[i][5] = b1.y; acc[i][6] = b1.z; acc[i][7] = b1.w;
    }
}

// acc[i][j] += sum_k A[i*128+k] * WT[k*128 + d0+j]
__device__ __forceinline__ void mm_acc(float acc[8][8], const float* __restrict__ WT,
                                       const float* __restrict__ A, int d0) {
#pragma unroll 2
    for (int k = 0; k < 128; k++) {
        float4 w0 = *(const float4*)(WT + k * DK + d0);
        float4 w1 = *(const float4*)(WT + k * DK + d0 + 4);
#pragma unroll
        for (int i = 0; i < 8; i++) {
            float av = A[i * DK + k];
            acc[i][0] = fmaf(av, w0.x, acc[i][0]);
            acc[i][1] = fmaf(av, w0.y, acc[i][1]);
            acc[i][2] = fmaf(av, w0.z, acc[i][2]);
            acc[i][3] = fmaf(av, w0.w, acc[i][3]);
            acc[i][4] = fmaf(av, w1.x, acc[i][4]);
            acc[i][5] = fmaf(av, w1.y, acc[i][5]);
            acc[i][6] = fmaf(av, w1.z, acc[i][6]);
            acc[i][7] = fmaf(av, w1.w, acc[i][7]);
        }
    }
}

__device__ __forceinline__ void acc_store(const float acc[8][8], float* __restrict__ dst,
                                          int b, int t0, int d0) {
#pragma unroll
    for (int i = 0; i < 8; i++) {
        float4 o0 = { acc[i][0], acc[i][1], acc[i][2], acc[i][3] };
        float4 o1 = { acc[i][4], acc[i][5], acc[i][6], acc[i][7] };
        float* p = dst + ((b * SS) + (t0 + i)) * DK + d0;
        *(float4*)p = o0;
        *(float4*)(p + 4) = o1;
    }
}

// ---------------- K_AL: all_learning = e@W1a^T + at@W1b^T + a*r1 + b1 ----------------
__global__ void __launch_bounds__(256) k_al(const int* __restrict__ e_data,
                                            const int* __restrict__ a_data,
                                            const int* __restrict__ at_data,
                                            const float* __restrict__ e_w,
                                            const float* __restrict__ at_w,
                                            const float* __restrict__ b1) {
    extern __shared__ float sm[];
    float* sE  = sm;            // 128x128
    float* sAT = sm + 16384;    // 128x128
    __shared__ int s_ei[128];
    __shared__ int s_ai[128];
    __shared__ float s_a[128];

    int b = blockIdx.x, tid = threadIdx.x;
    if (tid < 128) {
        s_ei[tid] = e_data[b * SS + tid];
        s_ai[tid] = at_data[b * SS + tid];
        s_a[tid]  = (float)a_data[b * SS + tid];
    }
    __syncthreads();
    for (int idx = tid; idx < 16384; idx += 256) {
        int t = idx >> 7, k = idx & 127;
        sE[idx]  = e_w[s_ei[t] * DK + k];
        sAT[idx] = at_w[s_ai[t] * DK + k];
    }
    __syncthreads();

    int d0 = (tid & 15) * 8, t0 = (tid >> 4) * 8;
    float acc[8][8];
    acc_init(acc, b1, d0);
    mm_acc(acc, g_WT + W1aT * DK * DK, sE + t0 * DK, d0);
    mm_acc(acc, g_WT + W1bT * DK * DK, sAT + t0 * DK, d0);

    float4 r0 = *(const float4*)(g_r1 + d0);
    float4 r1v = *(const float4*)(g_r1 + d0 + 4);
#pragma unroll
    for (int i = 0; i < 8; i++) {
        float a = s_a[t0 + i];
        acc[i][0] += a * r0.x;  acc[i][1] += a * r0.y;
        acc[i][2] += a * r0.z;  acc[i][3] += a * r0.w;
        acc[i][4] += a * r1v.x; acc[i][5] += a * r1v.y;
        acc[i][6] += a * r1v.z; acc[i][7] += a * r1v.w;
    }
    acc_store(acc, g_AL, b, t0, d0);
}

// ---------------- K_P: precompute P2,P3,P4,P5 ----------------
// SMEM: pad row [0,128) zeroed, sAL [128, 16512), sX [16512, 32896)
__global__ void __launch_bounds__(256) k_p(const int* __restrict__ e_data,
                                           const int* __restrict__ it_data,
                                           const float* __restrict__ e_w,
                                           const float* __restrict__ it_w,
                                           const float* __restrict__ b2,
                                           const float* __restrict__ b3,
                                           const float* __restrict__ b4,
                                           const float* __restrict__ b5) {
    extern __shared__ float sm[];
    float* sAL = sm + 128;        // 128x128 (row -1 = zero pad)
    float* sX  = sm + 16512;      // 128x128 (it_emb, later e_next)
    __shared__ int s_ii[128];

    int b = blockIdx.x, tid = threadIdx.x;
    if (tid < 128) { s_ii[tid] = it_data[b * SS + tid]; sm[tid] = 0.f; }
    __syncthreads();
    for (int idx = tid; idx < 16384; idx += 256) {
        sAL[idx] = g_AL[b * 16384 + idx];
        sX[idx]  = it_w[s_ii[idx >> 7] * DK + (idx & 127)];
    }
    __syncthreads();

    int d0 = (tid & 15) * 8, t0 = (tid >> 4) * 8;
    float acc[8][8];

    // P2 = AL[t-1]@W2a^T + it@W2b^T + AL[t]@W2c^T + b2   (AL[-1] = zero pad row)
    acc_init(acc, b2, d0);
    mm_acc(acc, g_WT + W2aT * DK * DK, sAL + (t0 - 1) * DK, d0);
    mm_acc(acc, g_WT + W2bT * DK * DK, sX + t0 * DK, d0);
    mm_acc(acc, g_WT + W2cT * DK * DK, sAL + t0 * DK, d0);
    acc_store(acc, g_P2, b, t0, d0);

    // P3 likewise with W3
    acc_init(acc, b3, d0);
    mm_acc(acc, g_WT + W3aT * DK * DK, sAL + (t0 - 1) * DK, d0);
    mm_acc(acc, g_WT + W3bT * DK * DK, sX + t0 * DK, d0);
    mm_acc(acc, g_WT + W3cT * DK * DK, sAL + t0 * DK, d0);
    acc_store(acc, g_P3, b, t0, d0);

    // P4 = it@W4c^T + b4
    acc_init(acc, b4, d0);
    mm_acc(acc, g_WT + W4cT * DK * DK, sX + t0 * DK, d0);
    acc_store(acc, g_P4, b, t0, d0);

    // reload sX with e_emb[t+1]
    __syncthreads();
    if (tid < 128) s_ii[tid] = (tid < 127) ? e_data[b * SS + tid + 1] : 0;
    __syncthreads();
    for (int idx = tid; idx < 16384; idx += 256) {
        int t = idx >> 7;
        sX[idx] = (t < 127) ? e_w[s_ii[t] * DK + (idx & 127)] : 0.f;
    }
    __syncthreads();

    // P5 = e_next@W5a^T + b5
    acc_init(acc, b5, d0);
    mm_acc(acc, g_WT + W5aT * DK * DK, sX + t0 * DK, d0);
    acc_store(acc, g_P5, b, t0, d0);
}

// ---------------- main persistent scan kernel: 1 CTA per batch ----------------
// SMEM layout (floats):
//  sH   [0, 13312)      H state, 104 rows x 128
//  sW4  [13312, 29696)  W4a^T  [k][d]
//  ht   [29696, 29824)
//  LG   [29824, 29952)
//  cS   [29952, 30080)
//  arg  [30080, 30336)
//  qe   [30336, 30440)
//  qn   [30440, 30544)
//  htp  [30544, 31568)  per-warp h_tilde partials [8][128]
//  red  [31568, 31584)
#define SMEM_MAIN_FLOATS 31584

__global__ void __launch_bounds__(256, 1) k_main(const int* __restrict__ e_data,
                                                 const float* __restrict__ qm,
                                                 const float* __restrict__ h0,
                                                 float* __restrict__ out) {
    extern __shared__ float sm[];
    float* sH  = sm;
    float* sW4 = sm + NROWS * DK;
    float* ht  = sm + 29696;
    float* LG  = sm + 29824;
    float* cS  = sm + 29952;
    float* arg = sm + 30080;
    float* qe  = sm + 30336;
    float* qn  = sm + 30440;
    float* htp = sm + 30544;
    float* red = sm + 31568;

    const int b = blockIdx.x, tid = threadIdx.x;
    const int w = tid >> 5, l = tid & 31;

    const float* gW2dT = g_WT + W2dT * DK * DK;
    const float* gW3dT = g_WT + W3dT * DK * DK;
    const float* gW4bT = g_WT + W4bT * DK * DK;
    const float* gW5bT = g_WT + W5bT * DK * DK;

    // ---- init: H = h0 (pad rows zero), load W4a^T, q0, h_tilde0 ----
    for (int idx = tid; idx < NROWS * DK; idx += 256)
        sH[idx] = (idx < NQ * DK) ? h0[idx] : 0.f;
    for (int idx = tid; idx < DK * DK; idx += 256)
        sW4[idx] = g_WT[W4aT * DK * DK + idx];
    if (tid < NROWS) {
        int e0 = e_data[b * SS];
        qe[tid] = (tid < NQ) ? qm[e0 * NQ + tid] : 0.f;
    }
    __syncthreads();
    if (tid < 32) {
        float v = 0.f;
        for (int n = tid; n < NROWS; n += 32) v += qe[n];
#pragma unroll
        for (int o = 16; o; o >>= 1) v += __shfl_xor_sync(0xffffffffu, v, o);
        if (tid == 0) red[0] = v;
    }
    __syncthreads();
    if (tid < 128) {
        float a = 0.f;
        for (int n = 0; n < NQ; n++) a += qe[n] * sH[n * DK + tid];
        ht[tid] = a / red[0];
    }
    if (tid == 0) out[b * SS] = 0.f;
    __syncthreads();

    // ---- scan ----
    for (int t = 0; t < SS - 1; t++) {
        const int base = (b * SS + t) * DK;
        float p_a = 0.f, p4v = 0.f, p5v = 0.f;
        if (tid < 128) {
            p_a = g_P2[base + tid];
            p4v = g_P4[base + tid];
            p5v = g_P5[base + tid];
        } else {
            p_a = g_P3[base + tid - 128];
        }
        const int e_t  = e_data[b * SS + t];
        const int e_t1 = e_data[b * SS + t + 1];
        if (tid < NROWS) {
            qe[tid] = (tid < NQ) ? qm[e_t * NQ + tid] : 0.f;
        } else if (tid >= 128 && tid < 128 + NROWS) {
            int m = tid - 128;
            qn[m] = (m < NQ) ? qm[e_t1 * NQ + m] : 0.f;
        }
        __syncthreads();

        // S1: lg/gl matvecs (tid<128 -> W2d, tid>=128 -> W3d) + qnsum on warp0
        {
            const float* WT = (tid < 128) ? gW2dT : gW3dT;
            int d = tid & 127;
            float a0 = p_a, a1 = 0.f, a2 = 0.f, a3 = 0.f;
#pragma unroll 4
            for (int k = 0; k < 128; k += 4) {
                a0 = fmaf(ht[k],     WT[(k)     * DK + d], a0);
                a1 = fmaf(ht[k + 1], WT[(k + 1) * DK + d], a1);
                a2 = fmaf(ht[k + 2], WT[(k + 2) * DK + d], a2);
                a3 = fmaf(ht[k + 3], WT[(k + 3) * DK + d], a3);
            }
            arg[tid] = (a0 + a1) + (a2 + a3);
        }
        if (tid < 32) {
            float v = 0.f;
            for (int n = tid; n < NROWS; n += 32) v += qn[n];
#pragma unroll
            for (int o = 16; o; o >>= 1) v += __shfl_xor_sync(0xffffffffu, v, o);
            if (tid == 0) red[0] = v;
        }
        __syncthreads();

        // S2: LG
        if (tid < 128) {
            float lg = tanhf(arg[tid]);
            float gl = sigmoidf(arg[128 + tid]);
            LG[tid] = gl * (lg + 1.f) * 0.5f;
        }
        __syncthreads();

        // S3: c = P4 + LG @ W4b^T   (split-k over 256 threads)
        {
            int d = tid & 127, h = tid >> 7;
            const float* Wp = gW4bT + h * 64 * DK;
            const float* lgp = LG + h * 64;
            float a0 = h ? 0.f : p4v, a1 = 0.f;
#pragma unroll 4
            for (int k = 0; k < 64; k += 2) {
                a0 = fmaf(lgp[k],     Wp[(k)     * DK + d], a0);
                a1 = fmaf(lgp[k + 1], Wp[(k + 1) * DK + d], a1);
            }
            arg[tid] = a0 + a1;
        }
        __syncthreads();
        if (tid < 128) cS[tid] = arg[tid] + arg[128 + tid];
        __syncthreads();

        // S4: big GEMM  gamma_f = sigmoid(H@W4a^T + c), H update, h_tilde partials
        {
            const float* hrow = sH + (13 * w) * DK;
            float4 lgv = *(const float4*)(LG + 4 * l);
            float4 cv  = *(const float4*)(cS + 4 * l);
            float4 acc[13];
#pragma unroll
            for (int i = 0; i < 13; i++) acc[i] = cv;
#pragma unroll 2
            for (int k = 0; k < 128; k++) {
                float4 wv = *(const float4*)(sW4 + k * DK + 4 * l);
#pragma unroll
                for (int i = 0; i < 13; i++) {
                    float hk = hrow[i * DK + k];
                    acc[i].x = fmaf(hk, wv.x, acc[i].x);
                    acc[i].y = fmaf(hk, wv.y, acc[i].y);
                    acc[i].z = fmaf(hk, wv.z, acc[i].z);
                    acc[i].w = fmaf(hk, wv.w, acc[i].w);
                }
            }
            __syncwarp();
            float4 pt = make_float4(0.f, 0.f, 0.f, 0.f);
#pragma unroll
            for (int i = 0; i < 13; i++) {
                int n = 13 * w + i;
                float* hp = sH + n * DK + 4 * l;
                float4 hv = *(float4*)hp;
                float qv = qe[n], qq = qn[n];
                float4 hn;
                hn.x = qv * lgv.x + sigmoidf(acc[i].x) * hv.x;
                hn.y = qv * lgv.y + sigmoidf(acc[i].y) * hv.y;
                hn.z = qv * lgv.z + sigmoidf(acc[i].z) * hv.z;
                hn.w = qv * lgv.w + sigmoidf(acc[i].w) * hv.w;
                *(float4*)hp = hn;
                pt.x = fmaf(qq, hn.x, pt.x);
                pt.y = fmaf(qq, hn.y, pt.y);
                pt.z = fmaf(qq, hn.z, pt.z);
                pt.w = fmaf(qq, hn.w, pt.w);
            }
            *(float4*)(htp + w * DK + 4 * l) = pt;
        }
        __syncthreads();

        // S5: h_tilde = (sum_w partials) / qnsum
        if (tid < 128) {
            float s = 0.f;
#pragma unroll
            for (int ww = 0; ww < 8; ww++) s += htp[ww * DK + tid];
            ht[tid] = s / red[0];
        }
        __syncthreads();

        // S6: y = mean_d sigmoid(P5 + ht @ W5b^T)   (split-k)
        {
            int d = tid & 127, h = tid >> 7;
            const float* Wp = gW5bT + h * 64 * DK;
            const float* hp = ht + h * 64;
            float a0 = h ? 0.f : p5v, a1 = 0.f;
#pragma unroll 4
            for (int k = 0; k < 64; k += 2) {
                a0 = fmaf(hp[k],     Wp[(k)     * DK + d], a0);
                a1 = fmaf(hp[k + 1], Wp[(k + 1) * DK + d], a1);
            }
            arg[tid] = a0 + a1;
        }
        __syncthreads();
        float v = 0.f;
        if (tid < 128) v = sigmoidf(arg[tid] + arg[128 + tid]);
#pragma unroll
        for (int o = 16; o; o >>= 1) v += __shfl_xor_sync(0xffffffffu, v, o);
        if (tid < 128 && l == 0) red[8 + w] = v;
        __syncthreads();
        if (tid == 0)
            out[b * SS + t + 1] = (red[8] + red[9] + red[10] + red[11]) * (1.0f / 128.0f);
        __syncthreads();
    }
}

// ---------------- host launcher ----------------
extern "C" void kernel_launch(void* const* d_in, const int* in_sizes, int n_in,
                              void* d_out, int out_size) {
    (void)in_sizes; (void)n_in; (void)out_size;
    const int*   e_data  = (const int*)d_in[0];
    const int*   a_data  = (const int*)d_in[1];
    const int*   it_data = (const int*)d_in[2];
    const int*   at_data = (const int*)d_in[3];
    const float* qm      = (const float*)d_in[4];
    const float* e_w     = (const float*)d_in[5];
    const float* at_w    = (const float*)d_in[6];
    const float* it_w    = (const float*)d_in[7];
    const float* h0      = (const float*)d_in[8];
    const float* W1      = (const float*)d_in[9];
    const float* b1      = (const float*)d_in[10];
    const float* W2      = (const float*)d_in[11];
    const float* b2      = (const float*)d_in[12];
    const float* W3      = (const float*)d_in[13];
    const float* b3      = (const float*)d_in[14];
    const float* W4      = (const float*)d_in[15];
    const float* b4      = (const float*)d_in[16];
    const float* W5      = (const float*)d_in[17];
    const float* b5      = (const float*)d_in[18];
    float* out = (float*)d_out;

    const int smem_al   = 2 * 128 * 128 * (int)sizeof(float);            // 131072
    const int smem_p    = (2 * 128 * 128 + 128) * (int)sizeof(float);    // 131584
    const int smem_main = SMEM_MAIN_FLOATS * (int)sizeof(float);         // 126336

    cudaFuncSetAttribute(k_al,   cudaFuncAttributeMaxDynamicSharedMemorySize, smem_al);
    cudaFuncSetAttribute(k_p,    cudaFuncAttributeMaxDynamicSharedMemorySize, smem_p);
    cudaFuncSetAttribute(k_main, cudaFuncAttributeMaxDynamicSharedMemorySize, smem_main);

    k_transpose<<<15, 256>>>(W1, W2, W3, W4, W5);
    k_al<<<BB, 256, smem_al>>>(e_data, a_data, at_data, e_w, at_w, b1);
    k_p<<<BB, 256, smem_p>>>(e_data, it_data, e_w, it_w, b2, b3, b4, b5);
    k_main<<<BB, 256, smem_main>>>(e_data, qm, h0, out);
}

// round 8
// speedup vs baseline: 1.4533x; 1.4533x over previous
#include <cuda_runtime.h>
#include <cstdint>

#define DK 128
#define BB 128
#define SS 128
#define NQ 101

// ---------------- device-global scratch (no runtime allocation) ----------------
__device__ float g_AL[BB * SS * DK];   // all_learning
__device__ float g_P2[BB * SS * DK];   // precomputed z@W2 (non-recurrent part) + b2
__device__ float g_P3[BB * SS * DK];
__device__ float g_P4[BB * SS * DK];   // it@W4c^T + b4
__device__ float g_P5[BB * SS * DK];   // e_next@W5a^T + b5
__device__ float g_WT[15 * DK * DK];   // transposed 128x128 weight slices [k][d]
__device__ float g_r1[DK];             // rowsum of W1[:,256:384]

// WT slice ids
#define W1aT 0
#define W1bT 1
#define W2aT 2
#define W2bT 3
#define W2cT 4
#define W2dT 5
#define W3aT 6
#define W3bT 7
#define W3cT 8
#define W3dT 9
#define W4aT 10
#define W4bT 11
#define W4cT 12
#define W5aT 13
#define W5bT 14

__device__ __forceinline__ float sigmoidf(float x) { return 1.0f / (1.0f + __expf(-x)); }

// tf32 mma: D += A * B  (A 16x8 row-major, B 8x8 col-major), fp32 acc
__device__ __forceinline__ void mma8(float* acc, const uint32_t* a, uint32_t b0, uint32_t b1) {
    asm volatile(
        "mma.sync.aligned.m16n8k8.row.col.f32.tf32.tf32.f32 "
        "{%0,%1,%2,%3}, {%4,%5,%6,%7}, {%8,%9}, {%0,%1,%2,%3};"
        : "+f"(acc[0]), "+f"(acc[1]), "+f"(acc[2]), "+f"(acc[3])
        : "r"(a[0]), "r"(a[1]), "r"(a[2]), "r"(a[3]), "r"(b0), "r"(b1));
}

__device__ __forceinline__ uint32_t tf32_hi(float v) {
    uint32_t r;
    asm("cvt.rna.tf32.f32 %0, %1;" : "=r"(r) : "f"(v));
    return r;
}

// ---------------- transpose kernel: build WT slices + r1 ----------------
__global__ void k_transpose(const float* __restrict__ W1, const float* __restrict__ W2,
                            const float* __restrict__ W3, const float* __restrict__ W4,
                            const float* __restrict__ W5) {
    int m = blockIdx.x;
    const float* src; int ld, off;
    switch (m) {
        case 0:  src = W1; ld = 384; off = 0;   break;
        case 1:  src = W1; ld = 384; off = 128; break;
        case 2:  src = W2; ld = 512; off = 0;   break;
        case 3:  src = W2; ld = 512; off = 128; break;
        case 4:  src = W2; ld = 512; off = 256; break;
        case 5:  src = W2; ld = 512; off = 384; break;
        case 6:  src = W3; ld = 512; off = 0;   break;
        case 7:  src = W3; ld = 512; off = 128; break;
        case 8:  src = W3; ld = 512; off = 256; break;
        case 9:  src = W3; ld = 512; off = 384; break;
        case 10: src = W4; ld = 384; off = 0;   break;
        case 11: src = W4; ld = 384; off = 128; break;
        case 12: src = W4; ld = 384; off = 256; break;
        case 13: src = W5; ld = 256; off = 0;   break;
        default: src = W5; ld = 256; off = 128; break;
    }
    float* dst = g_WT + m * DK * DK;
    for (int idx = threadIdx.x; idx < DK * DK; idx += blockDim.x) {
        int d = idx >> 7, k = idx & 127;
        dst[k * DK + d] = src[d * ld + off + k];
    }
    if (m == 0) {
        for (int d = threadIdx.x; d < DK; d += blockDim.x) {
            float s = 0.f;
            for (int j = 0; j < 128; j++) s += W1[d * 384 + 256 + j];
            g_r1[d] = s;
        }
    }
}

// ---------------- GEMM helpers for prologue (8t x 8d register blocking) ----------------
__device__ __forceinline__ void acc_init(float acc[8][8], const float* __restrict__ bias, int d0) {
    float4 b0 = *(const float4*)(bias + d0);
    float4 b1 = *(const float4*)(bias + d0 + 4);
#pragma unroll
    for (int i = 0; i < 8; i++) {
        acc[i][0] = b0.x; acc[i][1] = b0.y; acc[i][2] = b0.z; acc[i][3] = b0.w;
        acc[i][4] = b1.x; acc[i][5] = b1.y; acc[i][6] = b1.z; acc[i][7] = b1.w;
    }
}

__device__ __forceinline__ void mm_acc(float acc[8][8], const float* __restrict__ WT,
                                       const float* __restrict__ A, int d0) {
#pragma unroll 2
    for (int k = 0; k < 128; k++) {
        float4 w0 = *(const float4*)(WT + k * DK + d0);
        float4 w1 = *(const float4*)(WT + k * DK + d0 + 4);
#pragma unroll
        for (int i = 0; i < 8; i++) {
            float av = A[i * DK + k];
            acc[i][0] = fmaf(av, w0.x, acc[i][0]);
            acc[i][1] = fmaf(av, w0.y, acc[i][1]);
            acc[i][2] = fmaf(av, w0.z, acc[i][2]);
            acc[i][3] = fmaf(av, w0.w, acc[i][3]);
            acc[i][4] = fmaf(av, w1.x, acc[i][4]);
            acc[i][5] = fmaf(av, w1.y, acc[i][5]);
            acc[i][6] = fmaf(av, w1.z, acc[i][6]);
            acc[i][7] = fmaf(av, w1.w, acc[i][7]);
        }
    }
}

__device__ __forceinline__ void acc_store(const float acc[8][8], float* __restrict__ dst,
                                          int b, int t0, int d0) {
#pragma unroll
    for (int i = 0; i < 8; i++) {
        float4 o0 = { acc[i][0], acc[i][1], acc[i][2], acc[i][3] };
        float4 o1 = { acc[i][4], acc[i][5], acc[i][6], acc[i][7] };
        float* p = dst + ((b * SS) + (t0 + i)) * DK + d0;
        *(float4*)p = o0;
        *(float4*)(p + 4) = o1;
    }
}

// ---------------- K_AL ----------------
__global__ void __launch_bounds__(256) k_al(const int* __restrict__ e_data,
                                            const int* __restrict__ a_data,
                                            const int* __restrict__ at_data,
                                            const float* __restrict__ e_w,
                                            const float* __restrict__ at_w,
                                            const float* __restrict__ b1) {
    extern __shared__ float sm[];
    float* sE  = sm;
    float* sAT = sm + 16384;
    __shared__ int s_ei[128];
    __shared__ int s_ai[128];
    __shared__ float s_a[128];

    int b = blockIdx.x, tid = threadIdx.x;
    if (tid < 128) {
        s_ei[tid] = e_data[b * SS + tid];
        s_ai[tid] = at_data[b * SS + tid];
        s_a[tid]  = (float)a_data[b * SS + tid];
    }
    __syncthreads();
    for (int idx = tid; idx < 16384; idx += 256) {
        int t = idx >> 7, k = idx & 127;
        sE[idx]  = e_w[s_ei[t] * DK + k];
        sAT[idx] = at_w[s_ai[t] * DK + k];
    }
    __syncthreads();

    int d0 = (tid & 15) * 8, t0 = (tid >> 4) * 8;
    float acc[8][8];
    acc_init(acc, b1, d0);
    mm_acc(acc, g_WT + W1aT * DK * DK, sE + t0 * DK, d0);
    mm_acc(acc, g_WT + W1bT * DK * DK, sAT + t0 * DK, d0);

    float4 r0 = *(const float4*)(g_r1 + d0);
    float4 r1v = *(const float4*)(g_r1 + d0 + 4);
#pragma unroll
    for (int i = 0; i < 8; i++) {
        float a = s_a[t0 + i];
        acc[i][0] += a * r0.x;  acc[i][1] += a * r0.y;
        acc[i][2] += a * r0.z;  acc[i][3] += a * r0.w;
        acc[i][4] += a * r1v.x; acc[i][5] += a * r1v.y;
        acc[i][6] += a * r1v.z; acc[i][7] += a * r1v.w;
    }
    acc_store(acc, g_AL, b, t0, d0);
}

// ---------------- K_P ----------------
__global__ void __launch_bounds__(256) k_p(const int* __restrict__ e_data,
                                           const int* __restrict__ it_data,
                                           const float* __restrict__ e_w,
                                           const float* __restrict__ it_w,
                                           const float* __restrict__ b2,
                                           const float* __restrict__ b3,
                                           const float* __restrict__ b4,
                                           const float* __restrict__ b5) {
    extern __shared__ float sm[];
    float* sAL = sm + 128;        // row -1 = zero pad
    float* sX  = sm + 16512;
    __shared__ int s_ii[128];

    int b = blockIdx.x, tid = threadIdx.x;
    if (tid < 128) { s_ii[tid] = it_data[b * SS + tid]; sm[tid] = 0.f; }
    __syncthreads();
    for (int idx = tid; idx < 16384; idx += 256) {
        sAL[idx] = g_AL[b * 16384 + idx];
        sX[idx]  = it_w[s_ii[idx >> 7] * DK + (idx & 127)];
    }
    __syncthreads();

    int d0 = (tid & 15) * 8, t0 = (tid >> 4) * 8;
    float acc[8][8];

    acc_init(acc, b2, d0);
    mm_acc(acc, g_WT + W2aT * DK * DK, sAL + (t0 - 1) * DK, d0);
    mm_acc(acc, g_WT + W2bT * DK * DK, sX + t0 * DK, d0);
    mm_acc(acc, g_WT + W2cT * DK * DK, sAL + t0 * DK, d0);
    acc_store(acc, g_P2, b, t0, d0);

    acc_init(acc, b3, d0);
    mm_acc(acc, g_WT + W3aT * DK * DK, sAL + (t0 - 1) * DK, d0);
    mm_acc(acc, g_WT + W3bT * DK * DK, sX + t0 * DK, d0);
    mm_acc(acc, g_WT + W3cT * DK * DK, sAL + t0 * DK, d0);
    acc_store(acc, g_P3, b, t0, d0);

    acc_init(acc, b4, d0);
    mm_acc(acc, g_WT + W4cT * DK * DK, sX + t0 * DK, d0);
    acc_store(acc, g_P4, b, t0, d0);

    __syncthreads();
    if (tid < 128) s_ii[tid] = (tid < 127) ? e_data[b * SS + tid + 1] : 0;
    __syncthreads();
    for (int idx = tid; idx < 16384; idx += 256) {
        int t = idx >> 7;
        sX[idx] = (t < 127) ? e_w[s_ii[t] * DK + (idx & 127)] : 0.f;
    }
    __syncthreads();

    acc_init(acc, b5, d0);
    mm_acc(acc, g_WT + W5aT * DK * DK, sX + t0 * DK, d0);
    acc_store(acc, g_P5, b, t0, d0);
}

// ---------------- main scan kernel ----------------
// SMEM (float idx):
//  Hs   [0, 20480)       128 rows x 160 (permuted: addr(n,k)=n*160 + k + 4*(n&7))
//  sWhi [20480, 36864)   W4a hi, layout [kt][d][rr]: kt*1024 + d*8 + rr
//  sWlo [36864, 53248)   W4a lo residual, same layout
//  ht   [53248, 53376)
//  LG   [53376, 53504)
//  cS   [53504, 53632)
//  arg  [53632, 53888)
//  qe   [53888, 54016)
//  qn   [54016, 54144)
//  htp  [54144, 54272)
//  red  [54272, 54288)
#define HS_F   0
#define WHI_F  20480
#define WLO_F  36864
#define HT_F   53248
#define LG_F   53376
#define CS_F   53504
#define ARG_F  53632
#define QE_F   53888
#define QN_F   54016
#define HTP_F  54144
#define RED_F  54272
#define SMEM_MAIN_FLOATS 54288

__global__ void __launch_bounds__(256, 1) k_main(const int* __restrict__ e_data,
                                                 const float* __restrict__ qm,
                                                 const float* __restrict__ h0,
                                                 const float* __restrict__ W4,
                                                 float* __restrict__ out) {
    extern __shared__ float sm[];
    float* Hs   = sm + HS_F;
    float* sWhi = sm + WHI_F;
    float* sWlo = sm + WLO_F;
    float* ht   = sm + HT_F;
    float* LG   = sm + LG_F;
    float* cS   = sm + CS_F;
    float* arg  = sm + ARG_F;
    float* qe   = sm + QE_F;
    float* qn   = sm + QN_F;
    float* htp  = sm + HTP_F;
    float* red  = sm + RED_F;

    const int b = blockIdx.x, tid = threadIdx.x;
    const int w = tid >> 5, l = tid & 31;
    const int u = l >> 2, r = l & 3;
    const int d0 = 16 * w + u;              // this thread's d rows: d0, d0+8

    const float* gW2dT = g_WT + W2dT * DK * DK;
    const float* gW3dT = g_WT + W3dT * DK * DK;
    const float* gW4bT = g_WT + W4bT * DK * DK;
    const float* gW5bT = g_WT + W5bT * DK * DK;

    // ---- SMEM init: W4a hi/lo (tf32 split), H (permuted), qe, ht0 ----
    for (int idx = tid; idx < DK * DK; idx += 256) {
        int d = idx >> 7, k = idx & 127;
        float v = W4[d * 384 + k];
        float hi = __uint_as_float(tf32_hi(v));
        int dst = (k >> 3) * 1024 + d * 8 + (k & 7);
        sWhi[dst] = hi;
        sWlo[dst] = v - hi;
    }
    for (int idx = tid; idx < DK * DK; idx += 256) {
        int n = idx >> 7, k = idx & 127;
        Hs[n * 160 + k + 4 * (n & 7)] = (n < NQ) ? h0[n * DK + k] : 0.f;
    }
    if (tid < 128) {
        int e0 = e_data[b * SS];
        qe[tid] = (tid < NQ) ? qm[e0 * NQ + tid] : 0.f;
        qn[tid] = 0.f;
    }
    __syncthreads();
    if (tid < 32) {
        float v = 0.f;
        for (int n = tid; n < NQ; n += 32) v += qe[n];
#pragma unroll
        for (int o = 16; o; o >>= 1) v += __shfl_xor_sync(0xffffffffu, v, o);
        if (tid == 0) red[0] = v;
    }
    __syncthreads();
    if (tid < 128) {
        float a = 0.f;
        for (int n = 0; n < NQ; n++) a += qe[n] * h0[n * DK + tid];
        ht[tid] = a / red[0];
    }
    if (tid == 0) out[b * SS] = 0.f;
    __syncthreads();

    // per-thread B-frag base (floats): u*164 + r
    const int btb = u * 164 + r;
    // per-thread A-frag base within a kt block: d0*8 + r
    const int atb = d0 * 8 + r;

    // ---- scan ----
    for (int t = 0; t < SS - 1; t++) {
        const int base = (b * SS + t) * DK;
        float p_a = 0.f, p4v = 0.f, p5v = 0.f;
        if (tid < 128) {
            p_a = g_P2[base + tid];
            p4v = g_P4[base + tid];
            p5v = g_P5[base + tid];
        } else {
            p_a = g_P3[base + tid - 128];
        }
        const int e_t  = e_data[b * SS + t];
        const int e_t1 = e_data[b * SS + t + 1];
        if (tid < 128) {
            qe[tid] = (tid < NQ) ? qm[e_t * NQ + tid] : 0.f;
        } else {
            int m = tid - 128;
            qn[m] = (m < NQ) ? qm[e_t1 * NQ + m] : 0.f;
        }
        __syncthreads();

        // S1: arg = P + W{2,3}d . ht   (global weights, L2-hot; 8 accumulators)
        {
            const float* WT = (tid < 128) ? gW2dT : gW3dT;
            int d = tid & 127;
            float a0 = p_a, a1 = 0.f, a2 = 0.f, a3 = 0.f, a4 = 0.f, a5 = 0.f, a6 = 0.f, a7 = 0.f;
#pragma unroll
            for (int k = 0; k < 128; k += 8) {
                a0 = fmaf(ht[k + 0], WT[(k + 0) * DK + d], a0);
                a1 = fmaf(ht[k + 1], WT[(k + 1) * DK + d], a1);
                a2 = fmaf(ht[k + 2], WT[(k + 2) * DK + d], a2);
                a3 = fmaf(ht[k + 3], WT[(k + 3) * DK + d], a3);
                a4 = fmaf(ht[k + 4], WT[(k + 4) * DK + d], a4);
                a5 = fmaf(ht[k + 5], WT[(k + 5) * DK + d], a5);
                a6 = fmaf(ht[k + 6], WT[(k + 6) * DK + d], a6);
                a7 = fmaf(ht[k + 7], WT[(k + 7) * DK + d], a7);
            }
            arg[tid] = ((a0 + a1) + (a2 + a3)) + ((a4 + a5) + (a6 + a7));
        }
        if (tid < 32) {
            float v = 0.f;
            for (int n = tid; n < NQ; n += 32) v += qn[n];
#pragma unroll
            for (int o = 16; o; o >>= 1) v += __shfl_xor_sync(0xffffffffu, v, o);
            if (tid == 0) red[0] = v;
        }
        __syncthreads();

        // S2: LG
        if (tid < 128) {
            float lg = tanhf(arg[tid]);
            float gl = sigmoidf(arg[128 + tid]);
            LG[tid] = gl * (lg + 1.f) * 0.5f;
        }
        __syncthreads();

        // S3: cS = P4 + LG @ W4b^T (split-k)
        {
            int d = tid & 127, h = tid >> 7;
            const float* Wp = gW4bT + h * 64 * DK;
            const float* lgp = LG + h * 64;
            float a0 = h ? 0.f : p4v, a1 = 0.f, a2 = 0.f, a3 = 0.f;
#pragma unroll
            for (int k = 0; k < 64; k += 4) {
                a0 = fmaf(lgp[k + 0], Wp[(k + 0) * DK + d], a0);
                a1 = fmaf(lgp[k + 1], Wp[(k + 1) * DK + d], a1);
                a2 = fmaf(lgp[k + 2], Wp[(k + 2) * DK + d], a2);
                a3 = fmaf(lgp[k + 3], Wp[(k + 3) * DK + d], a3);
            }
            arg[tid] = (a0 + a1) + (a2 + a3);
        }
        __syncthreads();
        if (tid < 128) cS[tid] = arg[tid] + arg[128 + tid];
        __syncthreads();

        // S4a: tensor GEMM  D'[d,n] = W4a_hi.H^T + W4a_lo.H^T  (acc in regs, kt loop dynamic)
        float acc[16][4];
#pragma unroll
        for (int nt = 0; nt < 16; nt++) { acc[nt][0] = 0.f; acc[nt][1] = 0.f; acc[nt][2] = 0.f; acc[nt][3] = 0.f; }
        {
            const uint32_t* Hu = (const uint32_t*)Hs;
            for (int kt = 0; kt < 16; kt++) {
                const int ab = kt * 1024 + atb;
                uint32_t ahi[4], alo[4];
                ahi[0] = __float_as_uint(sWhi[ab]);
                ahi[1] = __float_as_uint(sWhi[ab + 64]);
                ahi[2] = __float_as_uint(sWhi[ab + 4]);
                ahi[3] = __float_as_uint(sWhi[ab + 68]);
                alo[0] = __float_as_uint(sWlo[ab]);
                alo[1] = __float_as_uint(sWlo[ab + 64]);
                alo[2] = __float_as_uint(sWlo[ab + 4]);
                alo[3] = __float_as_uint(sWlo[ab + 68]);
                const uint32_t* Hk = Hu + btb + kt * 8;
#pragma unroll
                for (int nt = 0; nt < 16; nt++) {
                    uint32_t b0 = Hk[nt * 1280];
                    uint32_t b1 = Hk[nt * 1280 + 4];
                    mma8(acc[nt], ahi, b0, b1);
                    mma8(acc[nt], alo, b0, b1);
                }
            }
        }
        __syncthreads();   // all H reads complete before epilogue writes

        // S4b epilogue: gamma=sigmoid(D+cS[d]); H <- qe[n]*LG[d] + gamma*H; h_tilde partials
        {
            float cs0 = cS[d0], cs1 = cS[d0 + 8];
            float lg0 = LG[d0], lg1 = LG[d0 + 8];
            float s0 = 0.f, s1 = 0.f;
#pragma unroll
            for (int nt = 0; nt < 16; nt++) {
                int n0 = nt * 8 + 2 * r;
                float qe0 = qe[n0], qe1 = qe[n0 + 1];
                float qn0 = qn[n0], qn1 = qn[n0 + 1];
                float* p00 = &Hs[n0 * 160 + d0 + 8 * r];           // (n0,   d0)
                float* p01 = &Hs[(n0 + 1) * 160 + d0 + 8 * r + 4]; // (n0+1, d0)
                float h00 = p00[0], h10 = p00[8], h01 = p01[0], h11 = p01[8];
                float H00 = qe0 * lg0 + sigmoidf(acc[nt][0] + cs0) * h00;
                float H01 = qe1 * lg0 + sigmoidf(acc[nt][1] + cs0) * h01;
                float H10 = qe0 * lg1 + sigmoidf(acc[nt][2] + cs1) * h10;
                float H11 = qe1 * lg1 + sigmoidf(acc[nt][3] + cs1) * h11;
                p00[0] = H00; p01[0] = H01; p00[8] = H10; p01[8] = H11;
                s0 = fmaf(qn0, H00, fmaf(qn1, H01, s0));
                s1 = fmaf(qn0, H10, fmaf(qn1, H11, s1));
            }
            s0 += __shfl_xor_sync(0xffffffffu, s0, 1);
            s0 += __shfl_xor_sync(0xffffffffu, s0, 2);
            s1 += __shfl_xor_sync(0xffffffffu, s1, 1);
            s1 += __shfl_xor_sync(0xffffffffu, s1, 2);
            if (r == 0) { htp[d0] = s0; htp[d0 + 8] = s1; }
        }
        __syncthreads();

        // h_tilde
        if (tid < 128) ht[tid] = htp[tid] / red[0];
        __syncthreads();

        // S6: y = mean_d sigmoid(P5 + ht @ W5b^T) (split-k)
        {
            int d = tid & 127, h = tid >> 7;
            const float* Wp = gW5bT + h * 64 * DK;
            const float* hp = ht + h * 64;
            float a0 = h ? 0.f : p5v, a1 = 0.f, a2 = 0.f, a3 = 0.f;
#pragma unroll
            for (int k = 0; k < 64; k += 4) {
                a0 = fmaf(hp[k + 0], Wp[(k + 0) * DK + d], a0);
                a1 = fmaf(hp[k + 1], Wp[(k + 1) * DK + d], a1);
                a2 = fmaf(hp[k + 2], Wp[(k + 2) * DK + d], a2);
                a3 = fmaf(hp[k + 3], Wp[(k + 3) * DK + d], a3);
            }
            arg[tid] = (a0 + a1) + (a2 + a3);
        }
        __syncthreads();
        float v = 0.f;
        if (tid < 128) v = sigmoidf(arg[tid] + arg[128 + tid]);
#pragma unroll
        for (int o = 16; o; o >>= 1) v += __shfl_xor_sync(0xffffffffu, v, o);
        if (tid < 128 && l == 0) red[8 + w] = v;
        __syncthreads();
        if (tid == 0)
            out[b * SS + t + 1] = (red[8] + red[9] + red[10] + red[11]) * (1.0f / 128.0f);
        __syncthreads();
    }
}

// ---------------- host launcher ----------------
extern "C" void kernel_launch(void* const* d_in, const int* in_sizes, int n_in,
                              void* d_out, int out_size) {
    (void)in_sizes; (void)n_in; (void)out_size;
    const int*   e_data  = (const int*)d_in[0];
    const int*   a_data  = (const int*)d_in[1];
    const int*   it_data = (const int*)d_in[2];
    const int*   at_data = (const int*)d_in[3];
    const float* qm      = (const float*)d_in[4];
    const float* e_w     = (const float*)d_in[5];
    const float* at_w    = (const float*)d_in[6];
    const float* it_w    = (const float*)d_in[7];
    const float* h0      = (const float*)d_in[8];
    const float* W1      = (const float*)d_in[9];
    const float* b1      = (const float*)d_in[10];
    const float* W2      = (const float*)d_in[11];
    const float* b2      = (const float*)d_in[12];
    const float* W3      = (const float*)d_in[13];
    const float* b3      = (const float*)d_in[14];
    const float* W4      = (const float*)d_in[15];
    const float* b4      = (const float*)d_in[16];
    const float* W5      = (const float*)d_in[17];
    const float* b5      = (const float*)d_in[18];
    float* out = (float*)d_out;

    const int smem_al   = 2 * 128 * 128 * (int)sizeof(float);            // 131072
    const int smem_p    = (2 * 128 * 128 + 128) * (int)sizeof(float);    // 131584
    const int smem_main = SMEM_MAIN_FLOATS * (int)sizeof(float);         // 217152

    cudaFuncSetAttribute(k_al,   cudaFuncAttributeMaxDynamicSharedMemorySize, smem_al);
    cudaFuncSetAttribute(k_p,    cudaFuncAttributeMaxDynamicSharedMemorySize, smem_p);
    cudaFuncSetAttribute(k_main, cudaFuncAttributeMaxDynamicSharedMemorySize, smem_main);

    k_transpose<<<15, 256>>>(W1, W2, W3, W4, W5);
    k_al<<<BB, 256, smem_al>>>(e_data, a_data, at_data, e_w, at_w, b1);
    k_p<<<BB, 256, smem_p>>>(e_data, it_data, e_w, it_w, b2, b3, b4, b5);
    k_main<<<BB, 256, smem_main>>>(e_data, qm, h0, W4, out);
}

// round 10
// speedup vs baseline: 2.4163x; 1.6626x over previous
#include <cuda_runtime.h>
#include <cstdint>

#define DK 128
#define BB 128
#define SS 128
#define NQ 101

// ---------------- device-global scratch (no runtime allocation) ----------------
__device__ float g_AL[BB * SS * DK];   // all_learning
__device__ float g_P2[BB * SS * DK];   // precomputed z@W2 (non-recurrent part) + b2
__device__ float g_P3[BB * SS * DK];
__device__ float g_P4[BB * SS * DK];   // it@W4c^T + b4
__device__ float g_P5[BB * SS * DK];   // e_next@W5a^T + b5
__device__ float g_WT[15 * DK * DK];   // transposed 128x128 weight slices [k][d]
__device__ float g_r1[DK];             // rowsum of W1[:,256:384]

// WT slice ids
#define W1aT 0
#define W1bT 1
#define W2aT 2
#define W2bT 3
#define W2cT 4
#define W2dT 5
#define W3aT 6
#define W3bT 7
#define W3cT 8
#define W3dT 9
#define W4aT 10
#define W4bT 11
#define W4cT 12
#define W5aT 13
#define W5bT 14

__device__ __forceinline__ float sigmoidf(float x) { return 1.0f / (1.0f + __expf(-x)); }

__device__ __forceinline__ float fast_tanh(float x) {
    float y;
    asm("tanh.approx.f32 %0, %1;" : "=f"(y) : "f"(x));
    return y;
}
__device__ __forceinline__ float fast_sigmoid(float x) {
    return fmaf(fast_tanh(x * 0.5f), 0.5f, 0.5f);
}

// tf32 mma: D += A * B  (A 16x8 row-major, B 8x8 col-major), fp32 acc
__device__ __forceinline__ void mma8(float* acc, const uint32_t* a, uint32_t b0, uint32_t b1) {
    asm volatile(
        "mma.sync.aligned.m16n8k8.row.col.f32.tf32.tf32.f32 "
        "{%0,%1,%2,%3}, {%4,%5,%6,%7}, {%8,%9}, {%0,%1,%2,%3};"
        : "+f"(acc[0]), "+f"(acc[1]), "+f"(acc[2]), "+f"(acc[3])
        : "r"(a[0]), "r"(a[1]), "r"(a[2]), "r"(a[3]), "r"(b0), "r"(b1));
}

__device__ __forceinline__ uint32_t tf32_hi(float v) {
    uint32_t r;
    asm("cvt.rna.tf32.f32 %0, %1;" : "=r"(r) : "f"(v));
    return r;
}

// ---------------- transpose kernel: build WT slices + r1 ----------------
__global__ void k_transpose(const float* __restrict__ W1, const float* __restrict__ W2,
                            const float* __restrict__ W3, const float* __restrict__ W4,
                            const float* __restrict__ W5) {
    int m = blockIdx.x;
    const float* src; int ld, off;
    switch (m) {
        case 0:  src = W1; ld = 384; off = 0;   break;
        case 1:  src = W1; ld = 384; off = 128; break;
        case 2:  src = W2; ld = 512; off = 0;   break;
        case 3:  src = W2; ld = 512; off = 128; break;
        case 4:  src = W2; ld = 512; off = 256; break;
        case 5:  src = W2; ld = 512; off = 384; break;
        case 6:  src = W3; ld = 512; off = 0;   break;
        case 7:  src = W3; ld = 512; off = 128; break;
        case 8:  src = W3; ld = 512; off = 256; break;
        case 9:  src = W3; ld = 512; off = 384; break;
        case 10: src = W4; ld = 384; off = 0;   break;
        case 11: src = W4; ld = 384; off = 128; break;
        case 12: src = W4; ld = 384; off = 256; break;
        case 13: src = W5; ld = 256; off = 0;   break;
        default: src = W5; ld = 256; off = 128; break;
    }
    float* dst = g_WT + m * DK * DK;
    for (int idx = threadIdx.x; idx < DK * DK; idx += blockDim.x) {
        int d = idx >> 7, k = idx & 127;
        dst[k * DK + d] = src[d * ld + off + k];
    }
    if (m == 0) {
        for (int d = threadIdx.x; d < DK; d += blockDim.x) {
            float s = 0.f;
            for (int j = 0; j < 128; j++) s += W1[d * 384 + 256 + j];
            g_r1[d] = s;
        }
    }
}

// ---------------- GEMM helpers for prologue (8t x 8d register blocking) ----------------
__device__ __forceinline__ void acc_init(float acc[8][8], const float* __restrict__ bias, int d0) {
    float4 b0 = *(const float4*)(bias + d0);
    float4 b1 = *(const float4*)(bias + d0 + 4);
#pragma unroll
    for (int i = 0; i < 8; i++) {
        acc[i][0] = b0.x; acc[i][1] = b0.y; acc[i][2] = b0.z; acc[i][3] = b0.w;
        acc[i][4] = b1.x; acc[i][5] = b1.y; acc[i][6] = b1.z; acc[i][7] = b1.w;
    }
}

__device__ __forceinline__ void mm_acc(float acc[8][8], const float* __restrict__ WT,
                                       const float* __restrict__ A, int d0) {
#pragma unroll 2
    for (int k = 0; k < 128; k++) {
        float4 w0 = *(const float4*)(WT + k * DK + d0);
        float4 w1 = *(const float4*)(WT + k * DK + d0 + 4);
#pragma unroll
        for (int i = 0; i < 8; i++) {
            float av = A[i * DK + k];
            acc[i][0] = fmaf(av, w0.x, acc[i][0]);
            acc[i][1] = fmaf(av, w0.y, acc[i][1]);
            acc[i][2] = fmaf(av, w0.z, acc[i][2]);
            acc[i][3] = fmaf(av, w0.w, acc[i][3]);
            acc[i][4] = fmaf(av, w1.x, acc[i][4]);
            acc[i][5] = fmaf(av, w1.y, acc[i][5]);
            acc[i][6] = fmaf(av, w1.z, acc[i][6]);
            acc[i][7] = fmaf(av, w1.w, acc[i][7]);
        }
    }
}

__device__ __forceinline__ void acc_store(const float acc[8][8], float* __restrict__ dst,
                                          int b, int t0, int d0) {
#pragma unroll
    for (int i = 0; i < 8; i++) {
        float4 o0 = { acc[i][0], acc[i][1], acc[i][2], acc[i][3] };
        float4 o1 = { acc[i][4], acc[i][5], acc[i][6], acc[i][7] };
        float* p = dst + ((b * SS) + (t0 + i)) * DK + d0;
        *(float4*)p = o0;
        *(float4*)(p + 4) = o1;
    }
}

// ---------------- K_AL ----------------
__global__ void __launch_bounds__(256) k_al(const int* __restrict__ e_data,
                                            const int* __restrict__ a_data,
                                            const int* __restrict__ at_data,
                                            const float* __restrict__ e_w,
                                            const float* __restrict__ at_w,
                                            const float* __restrict__ b1) {
    extern __shared__ float sm[];
    float* sE  = sm;
    float* sAT = sm + 16384;
    __shared__ int s_ei[128];
    __shared__ int s_ai[128];
    __shared__ float s_a[128];

    int b = blockIdx.x, tid = threadIdx.x;
    if (tid < 128) {
        s_ei[tid] = e_data[b * SS + tid];
        s_ai[tid] = at_data[b * SS + tid];
        s_a[tid]  = (float)a_data[b * SS + tid];
    }
    __syncthreads();
    for (int idx = tid; idx < 16384; idx += 256) {
        int t = idx >> 7, k = idx & 127;
        sE[idx]  = e_w[s_ei[t] * DK + k];
        sAT[idx] = at_w[s_ai[t] * DK + k];
    }
    __syncthreads();

    int d0 = (tid & 15) * 8, t0 = (tid >> 4) * 8;
    float acc[8][8];
    acc_init(acc, b1, d0);
    mm_acc(acc, g_WT + W1aT * DK * DK, sE + t0 * DK, d0);
    mm_acc(acc, g_WT + W1bT * DK * DK, sAT + t0 * DK, d0);

    float4 r0 = *(const float4*)(g_r1 + d0);
    float4 r1v = *(const float4*)(g_r1 + d0 + 4);
#pragma unroll
    for (int i = 0; i < 8; i++) {
        float a = s_a[t0 + i];
        acc[i][0] += a * r0.x;  acc[i][1] += a * r0.y;
        acc[i][2] += a * r0.z;  acc[i][3] += a * r0.w;
        acc[i][4] += a * r1v.x; acc[i][5] += a * r1v.y;
        acc[i][6] += a * r1v.z; acc[i][7] += a * r1v.w;
    }
    acc_store(acc, g_AL, b, t0, d0);
}

// ---------------- K_P ----------------
__global__ void __launch_bounds__(256) k_p(const int* __restrict__ e_data,
                                           const int* __restrict__ it_data,
                                           const float* __restrict__ e_w,
                                           const float* __restrict__ it_w,
                                           const float* __restrict__ b2,
                                           const float* __restrict__ b3,
                                           const float* __restrict__ b4,
                                           const float* __restrict__ b5) {
    extern __shared__ float sm[];
    float* sAL = sm + 128;        // row -1 = zero pad
    float* sX  = sm + 16512;
    __shared__ int s_ii[128];

    int b = blockIdx.x, tid = threadIdx.x;
    if (tid < 128) { s_ii[tid] = it_data[b * SS + tid]; sm[tid] = 0.f; }
    __syncthreads();
    for (int idx = tid; idx < 16384; idx += 256) {
        sAL[idx] = g_AL[b * 16384 + idx];
        sX[idx]  = it_w[s_ii[idx >> 7] * DK + (idx & 127)];
    }
    __syncthreads();

    int d0 = (tid & 15) * 8, t0 = (tid >> 4) * 8;
    float acc[8][8];

    acc_init(acc, b2, d0);
    mm_acc(acc, g_WT + W2aT * DK * DK, sAL + (t0 - 1) * DK, d0);
    mm_acc(acc, g_WT + W2bT * DK * DK, sX + t0 * DK, d0);
    mm_acc(acc, g_WT + W2cT * DK * DK, sAL + t0 * DK, d0);
    acc_store(acc, g_P2, b, t0, d0);

    acc_init(acc, b3, d0);
    mm_acc(acc, g_WT + W3aT * DK * DK, sAL + (t0 - 1) * DK, d0);
    mm_acc(acc, g_WT + W3bT * DK * DK, sX + t0 * DK, d0);
    mm_acc(acc, g_WT + W3cT * DK * DK, sAL + t0 * DK, d0);
    acc_store(acc, g_P3, b, t0, d0);

    acc_init(acc, b4, d0);
    mm_acc(acc, g_WT + W4cT * DK * DK, sX + t0 * DK, d0);
    acc_store(acc, g_P4, b, t0, d0);

    __syncthreads();
    if (tid < 128) s_ii[tid] = (tid < 127) ? e_data[b * SS + tid + 1] : 0;
    __syncthreads();
    for (int idx = tid; idx < 16384; idx += 256) {
        int t = idx >> 7;
        sX[idx] = (t < 127) ? e_w[s_ii[t] * DK + (idx & 127)] : 0.f;
    }
    __syncthreads();

    acc_init(acc, b5, d0);
    mm_acc(acc, g_WT + W5aT * DK * DK, sX + t0 * DK, d0);
    acc_store(acc, g_P5, b, t0, d0);
}

// ---------------- main scan kernel ----------------
// SMEM (float idx):
//  Hs   [0, 20480)       128 rows x 160 (permuted: addr(n,k)=n*160 + k + 4*(n&7))
//  sWhi [20480, 36864)   W4a tf32-hi, layout [kt][d][rr]: kt*1024 + d*8 + rr
//  ht   [36864, 36992)
//  LG   [36992, 37120)
//  cS   [37120, 37248)
//  arg  [37248, 37504)
//  qe   [37504, 37632)
//  qn   [37632, 37760)
//  htp  [37760, 37888)
//  red  [37888, 37904)
#define HS_F   0
#define WHI_F  20480
#define HT_F   36864
#define LG_F   36992
#define CS_F   37120
#define ARG_F  37248
#define QE_F   37504
#define QN_F   37632
#define HTP_F  37760
#define RED_F  37888
#define SMEM_MAIN_FLOATS 37904

__global__ void __launch_bounds__(256, 1) k_main(const int* __restrict__ e_data,
                                                 const float* __restrict__ qm,
                                                 const float* __restrict__ h0,
                                                 const float* __restrict__ W4,
                                                 float* __restrict__ out) {
    extern __shared__ float sm[];
    float* Hs   = sm + HS_F;
    float* sWhi = sm + WHI_F;
    float* ht   = sm + HT_F;
    float* LG   = sm + LG_F;
    float* cS   = sm + CS_F;
    float* arg  = sm + ARG_F;
    float* qe   = sm + QE_F;
    float* qn   = sm + QN_F;
    float* htp  = sm + HTP_F;
    float* red  = sm + RED_F;

    const int b = blockIdx.x, tid = threadIdx.x;
    const int w = tid >> 5, l = tid & 31;
    const int u = l >> 2, r = l & 3;
    const int d0 = 16 * w + u;              // this thread's d rows: d0, d0+8

    const float* gW2dT = g_WT + W2dT * DK * DK;
    const float* gW3dT = g_WT + W3dT * DK * DK;
    const float* gW4bT = g_WT + W4bT * DK * DK;
    const float* gW5bT = g_WT + W5bT * DK * DK;

    // ---- SMEM init: W4a hi (tf32), H (permuted), initial qe, ht0 ----
    for (int idx = tid; idx < DK * DK; idx += 256) {
        int d = idx >> 7, k = idx & 127;
        float v = W4[d * 384 + k];
        sWhi[(k >> 3) * 1024 + d * 8 + (k & 7)] = __uint_as_float(tf32_hi(v));
    }
    for (int idx = tid; idx < DK * DK; idx += 256) {
        int n = idx >> 7, k = idx & 127;
        Hs[n * 160 + k + 4 * (n & 7)] = (n < NQ) ? h0[n * DK + k] : 0.f;
    }
    int eA = e_data[b * SS];          // qm row for qe at step t
    int eB = e_data[b * SS + 1];      // qm row for qn at step t
    if (tid < 128) {
        qe[tid] = (tid < NQ) ? qm[eA * NQ + tid] : 0.f;
        qn[tid] = 0.f;
    }
    __syncthreads();
    if (tid < 32) {
        float v = 0.f;
        for (int n = tid; n < NQ; n += 32) v += qe[n];
#pragma unroll
        for (int o = 16; o; o >>= 1) v += __shfl_xor_sync(0xffffffffu, v, o);
        if (tid == 0) red[0] = v;
    }
    __syncthreads();
    if (tid < 128) {
        float a = 0.f;
        for (int n = 0; n < NQ; n++) a += qe[n] * h0[n * DK + tid];
        ht[tid] = a / red[0];
    }
    if (tid == 0) out[b * SS] = 0.f;

    // ---- prefetch step-0 operands into registers ----
    float p_a, p4v = 0.f, p5v = 0.f, qv = 0.f, qnv = 0.f;
    {
        const int base = (b * SS) * DK;
        if (tid < 128) {
            p_a = g_P2[base + tid];
            p4v = g_P4[base + tid];
            p5v = g_P5[base + tid];
            qv  = (tid < NQ) ? qm[eA * NQ + tid] : 0.f;
        } else {
            p_a = g_P3[base + tid - 128];
            int m = tid - 128;
            qnv = (m < NQ) ? qm[eB * NQ + m] : 0.f;
        }
    }

    // per-thread B-frag base (floats): u*164 + r
    const int btb = u * 164 + r;
    // per-thread A-frag base within a kt block: d0*8 + r
    const int atb = d0 * 8 + r;

    // ---- scan ----
    for (int t = 0; t < SS - 1; t++) {
        __syncthreads();                        // sync1: Hs/ht from prev step final
        if (tid < 128) qe[tid] = qv;
        else           qn[tid - 128] = qnv;

        // S4a FIRST: tensor GEMM D'[d,n] = W4a_hi . H^T (single tf32 pass, acc in regs)
        // Runs on tensor pipe while S1 (FMA+LDG) executes below.
        float acc[16][4];
#pragma unroll
        for (int nt = 0; nt < 16; nt++) { acc[nt][0] = 0.f; acc[nt][1] = 0.f; acc[nt][2] = 0.f; acc[nt][3] = 0.f; }
        {
            const uint32_t* Hu = (const uint32_t*)Hs;
            for (int kt = 0; kt < 16; kt++) {
                const int ab = kt * 1024 + atb;
                uint32_t ahi[4];
                ahi[0] = __float_as_uint(sWhi[ab]);
                ahi[1] = __float_as_uint(sWhi[ab + 64]);
                ahi[2] = __float_as_uint(sWhi[ab + 4]);
                ahi[3] = __float_as_uint(sWhi[ab + 68]);
                const uint32_t* Hk = Hu + btb + kt * 8;
#pragma unroll
                for (int nt = 0; nt < 16; nt++) {
                    uint32_t b0 = Hk[nt * 1280];
                    uint32_t b1 = Hk[nt * 1280 + 4];
                    mma8(acc[nt], ahi, b0, b1);
                }
            }
        }

        // S1: arg = P + W{2,3}d . ht   (global weights, L2-hot; overlaps tensor)
        {
            const float* WT = (tid < 128) ? gW2dT : gW3dT;
            int d = tid & 127;
            float a0 = p_a, a1 = 0.f, a2 = 0.f, a3 = 0.f, a4 = 0.f, a5 = 0.f, a6 = 0.f, a7 = 0.f;
#pragma unroll
            for (int k = 0; k < 128; k += 8) {
                a0 = fmaf(ht[k + 0], WT[(k + 0) * DK + d], a0);
                a1 = fmaf(ht[k + 1], WT[(k + 1) * DK + d], a1);
                a2 = fmaf(ht[k + 2], WT[(k + 2) * DK + d], a2);
                a3 = fmaf(ht[k + 3], WT[(k + 3) * DK + d], a3);
                a4 = fmaf(ht[k + 4], WT[(k + 4) * DK + d], a4);
                a5 = fmaf(ht[k + 5], WT[(k + 5) * DK + d], a5);
                a6 = fmaf(ht[k + 6], WT[(k + 6) * DK + d], a6);
                a7 = fmaf(ht[k + 7], WT[(k + 7) * DK + d], a7);
            }
            arg[tid] = ((a0 + a1) + (a2 + a3)) + ((a4 + a5) + (a6 + a7));
        }
        __syncthreads();                        // sync2: arg + qn ready

        // S2 (tid<128) || qn-sum (warp 4 lanes)
        if (tid < 128) {
            float lg = fast_tanh(arg[tid]);
            float gl = fast_sigmoid(arg[128 + tid]);
            LG[tid] = gl * (lg + 1.f) * 0.5f;
        } else if (tid < 160) {
            int lane = tid - 128;
            float v = 0.f;
            for (int n = lane; n < NQ; n += 32) v += qn[n];
#pragma unroll
            for (int o = 16; o; o >>= 1) v += __shfl_xor_sync(0xffffffffu, v, o);
            if (lane == 0) red[0] = v;
        }
        __syncthreads();                        // sync3: LG ready

        // S3: cS = P4 + LG @ W4b^T (split-k over 256 threads)
        {
            int d = tid & 127, h = tid >> 7;
            const float* Wp = gW4bT + h * 64 * DK;
            const float* lgp = LG + h * 64;
            float a0 = h ? 0.f : p4v, a1 = 0.f, a2 = 0.f, a3 = 0.f;
#pragma unroll
            for (int k = 0; k < 64; k += 4) {
                a0 = fmaf(lgp[k + 0], Wp[(k + 0) * DK + d], a0);
                a1 = fmaf(lgp[k + 1], Wp[(k + 1) * DK + d], a1);
                a2 = fmaf(lgp[k + 2], Wp[(k + 2) * DK + d], a2);
                a3 = fmaf(lgp[k + 3], Wp[(k + 3) * DK + d], a3);
            }
            arg[tid] = (a0 + a1) + (a2 + a3);
        }
        __syncthreads();                        // sync4a
        if (tid < 128) cS[tid] = arg[tid] + arg[128 + tid];
        __syncthreads();                        // sync4b: cS ready; all MMA Hs-reads retired

        // S4b epilogue: gamma=sigmoid(D+cS[d]); H <- qe[n]*LG[d] + gamma*H; h_tilde partials
        {
            float cs0 = cS[d0], cs1 = cS[d0 + 8];
            float lg0 = LG[d0], lg1 = LG[d0 + 8];
            float s0 = 0.f, s1 = 0.f;
#pragma unroll
            for (int nt = 0; nt < 16; nt++) {
                int n0 = nt * 8 + 2 * r;
                float qe0 = qe[n0], qe1 = qe[n0 + 1];
                float qn0 = qn[n0], qn1 = qn[n0 + 1];
                float* p00 = &Hs[n0 * 160 + d0 + 8 * r];           // (n0,   d0)
                float* p01 = &Hs[(n0 + 1) * 160 + d0 + 8 * r + 4]; // (n0+1, d0)
                float h00 = p00[0], h10 = p00[8], h01 = p01[0], h11 = p01[8];
                float H00 = qe0 * lg0 + fast_sigmoid(acc[nt][0] + cs0) * h00;
                float H01 = qe1 * lg0 + fast_sigmoid(acc[nt][1] + cs0) * h01;
                float H10 = qe0 * lg1 + fast_sigmoid(acc[nt][2] + cs1) * h10;
                float H11 = qe1 * lg1 + fast_sigmoid(acc[nt][3] + cs1) * h11;
                p00[0] = H00; p01[0] = H01; p00[8] = H10; p01[8] = H11;
                s0 = fmaf(qn0, H00, fmaf(qn1, H01, s0));
                s1 = fmaf(qn0, H10, fmaf(qn1, H11, s1));
            }
            s0 += __shfl_xor_sync(0xffffffffu, s0, 1);
            s0 += __shfl_xor_sync(0xffffffffu, s0, 2);
            s1 += __shfl_xor_sync(0xffffffffu, s1, 1);
            s1 += __shfl_xor_sync(0xffffffffu, s1, 2);
            if (r == 0) { htp[d0] = s0; htp[d0 + 8] = s1; }
        }
        __syncthreads();                        // sync5: htp + Hs updated

        // h_tilde
        if (tid < 128) ht[tid] = htp[tid] / red[0];

        // ---- prefetch next step operands (overlaps S6 below) ----
        float p5cur = p5v;
        {
            int t2 = (t + 2 < SS) ? t + 2 : SS - 1;
            eA = eB;
            eB = e_data[b * SS + t2];
            const int base2 = (b * SS + t + 1) * DK;
            if (tid < 128) {
                p_a = g_P2[base2 + tid];
                p4v = g_P4[base2 + tid];
                p5v = g_P5[base2 + tid];
                qv  = (tid < NQ) ? qm[eA * NQ + tid] : 0.f;
            } else {
                p_a = g_P3[base2 + tid - 128];
                int m = tid - 128;
                qnv = (m < NQ) ? qm[eB * NQ + m] : 0.f;
            }
        }
        __syncthreads();                        // sync6: ht ready

        // S6: y = mean_d sigmoid(P5 + ht @ W5b^T) (split-k)
        {
            int d = tid & 127, h = tid >> 7;
            const float* Wp = gW5bT + h * 64 * DK;
            const float* hp = ht + h * 64;
            float a0 = h ? 0.f : p5cur, a1 = 0.f, a2 = 0.f, a3 = 0.f;
#pragma unroll
            for (int k = 0; k < 64; k += 4) {
                a0 = fmaf(hp[k + 0], Wp[(k + 0) * DK + d], a0);
                a1 = fmaf(hp[k + 1], Wp[(k + 1) * DK + d], a1);
                a2 = fmaf(hp[k + 2], Wp[(k + 2) * DK + d], a2);
                a3 = fmaf(hp[k + 3], Wp[(k + 3) * DK + d], a3);
            }
            arg[tid] = (a0 + a1) + (a2 + a3);
        }
        __syncthreads();                        // sync7
        float v = 0.f;
        if (tid < 128) v = fast_sigmoid(arg[tid] + arg[128 + tid]);
#pragma unroll
        for (int o = 16; o; o >>= 1) v += __shfl_xor_sync(0xffffffffu, v, o);
        if (tid < 128 && l == 0) red[8 + w] = v;
        __syncthreads();                        // sync8
        if (tid == 0)
            out[b * SS + t + 1] = (red[8] + red[9] + red[10] + red[11]) * (1.0f / 128.0f);
    }
}

// ---------------- host launcher ----------------
extern "C" void kernel_launch(void* const* d_in, const int* in_sizes, int n_in,
                              void* d_out, int out_size) {
    (void)in_sizes; (void)n_in; (void)out_size;
    const int*   e_data  = (const int*)d_in[0];
    const int*   a_data  = (const int*)d_in[1];
    const int*   it_data = (const int*)d_in[2];
    const int*   at_data = (const int*)d_in[3];
    const float* qm      = (const float*)d_in[4];
    const float* e_w     = (const float*)d_in[5];
    const float* at_w    = (const float*)d_in[6];
    const float* it_w    = (const float*)d_in[7];
    const float* h0      = (const float*)d_in[8];
    const float* W1      = (const float*)d_in[9];
    const float* b1      = (const float*)d_in[10];
    const float* W2      = (const float*)d_in[11];
    const float* b2      = (const float*)d_in[12];
    const float* W3      = (const float*)d_in[13];
    const float* b3      = (const float*)d_in[14];
    const float* W4      = (const float*)d_in[15];
    const float* b4      = (const float*)d_in[16];
    const float* W5      = (const float*)d_in[17];
    const float* b5      = (const float*)d_in[18];
    float* out = (float*)d_out;

    const int smem_al   = 2 * 128 * 128 * (int)sizeof(float);            // 131072
    const int smem_p    = (2 * 128 * 128 + 128) * (int)sizeof(float);    // 131584
    const int smem_main = SMEM_MAIN_FLOATS * (int)sizeof(float);         // 151616

    cudaFuncSetAttribute(k_al,   cudaFuncAttributeMaxDynamicSharedMemorySize, smem_al);
    cudaFuncSetAttribute(k_p,    cudaFuncAttributeMaxDynamicSharedMemorySize, smem_p);
    cudaFuncSetAttribute(k_main, cudaFuncAttributeMaxDynamicSharedMemorySize, smem_main);

    k_transpose<<<15, 256>>>(W1, W2, W3, W4, W5);
    k_al<<<BB, 256, smem_al>>>(e_data, a_data, at_data, e_w, at_w, b1);
    k_p<<<BB, 256, smem_p>>>(e_data, it_data, e_w, it_w, b2, b3, b4, b5);
    k_main<<<BB, 256, smem_main>>>(e_data, qm, h0, W4, out);
}

// round 12
// speedup vs baseline: 2.7461x; 1.1365x over previous
#include <cuda_runtime.h>
#include <cstdint>

#define DK 128
#define BB 128
#define SS 128
#define NQ 101

// ---------------- device-global scratch (no runtime allocation) ----------------
__device__ float g_AL[BB * SS * DK];   // all_learning
__device__ float g_P2[BB * SS * DK];   // precomputed z@W2 (non-recurrent part) + b2
__device__ float g_P3[BB * SS * DK];
__device__ float g_P4[BB * SS * DK];   // it@W4c^T + b4
__device__ float g_P5[BB * SS * DK];   // e_next@W5a^T + b5
__device__ float g_WT[15 * DK * DK];   // transposed 128x128 weight slices [k][d]
__device__ float g_r1[DK];             // rowsum of W1[:,256:384]

// WT slice ids
#define W1aT 0
#define W1bT 1
#define W2aT 2
#define W2bT 3
#define W2cT 4
#define W2dT 5
#define W3aT 6
#define W3bT 7
#define W3cT 8
#define W3dT 9
#define W4aT 10
#define W4bT 11
#define W4cT 12
#define W5aT 13
#define W5bT 14

__device__ __forceinline__ float fast_tanh(float x) {
    float y;
    asm("tanh.approx.f32 %0, %1;" : "=f"(y) : "f"(x));
    return y;
}
__device__ __forceinline__ float fast_sigmoid(float x) {
    return fmaf(fast_tanh(x * 0.5f), 0.5f, 0.5f);
}

// pack two fp32 into bf16x2 (lo = first arg, hi = second)
__device__ __forceinline__ uint32_t pack_bf16(float lo, float hi) {
    uint32_t r;
    asm("cvt.rn.bf16x2.f32 %0, %1, %2;" : "=r"(r) : "f"(hi), "f"(lo));
    return r;
}
__device__ __forceinline__ float bf_lo(uint32_t w) { return __uint_as_float(w << 16); }
__device__ __forceinline__ float bf_hi(uint32_t w) { return __uint_as_float(w & 0xFFFF0000u); }

// bf16 mma m16n8k16: D += A(16x16 row) * B(16x8 col), fp32 acc
__device__ __forceinline__ void mma16(float* acc, const uint32_t* a, uint32_t b0, uint32_t b1) {
    asm volatile(
        "mma.sync.aligned.m16n8k16.row.col.f32.bf16.bf16.f32 "
        "{%0,%1,%2,%3}, {%4,%5,%6,%7}, {%8,%9}, {%0,%1,%2,%3};"
        : "+f"(acc[0]), "+f"(acc[1]), "+f"(acc[2]), "+f"(acc[3])
        : "r"(a[0]), "r"(a[1]), "r"(a[2]), "r"(a[3]), "r"(b0), "r"(b1));
}

// ---------------- transpose kernel: build WT slices + r1 ----------------
__global__ void k_transpose(const float* __restrict__ W1, const float* __restrict__ W2,
                            const float* __restrict__ W3, const float* __restrict__ W4,
                            const float* __restrict__ W5) {
    int m = blockIdx.x;
    const float* src; int ld, off;
    switch (m) {
        case 0:  src = W1; ld = 384; off = 0;   break;
        case 1:  src = W1; ld = 384; off = 128; break;
        case 2:  src = W2; ld = 512; off = 0;   break;
        case 3:  src = W2; ld = 512; off = 128; break;
        case 4:  src = W2; ld = 512; off = 256; break;
        case 5:  src = W2; ld = 512; off = 384; break;
        case 6:  src = W3; ld = 512; off = 0;   break;
        case 7:  src = W3; ld = 512; off = 128; break;
        case 8:  src = W3; ld = 512; off = 256; break;
        case 9:  src = W3; ld = 512; off = 384; break;
        case 10: src = W4; ld = 384; off = 0;   break;
        case 11: src = W4; ld = 384; off = 128; break;
        case 12: src = W4; ld = 384; off = 256; break;
        case 13: src = W5; ld = 256; off = 0;   break;
        default: src = W5; ld = 256; off = 128; break;
    }
    float* dst = g_WT + m * DK * DK;
    for (int idx = threadIdx.x; idx < DK * DK; idx += blockDim.x) {
        int d = idx >> 7, k = idx & 127;
        dst[k * DK + d] = src[d * ld + off + k];
    }
    if (m == 0) {
        for (int d = threadIdx.x; d < DK; d += blockDim.x) {
            float s = 0.f;
            for (int j = 0; j < 128; j++) s += W1[d * 384 + 256 + j];
            g_r1[d] = s;
        }
    }
}

// ---------------- GEMM helpers for prologue (8t x 8d register blocking) ----------------
__device__ __forceinline__ void acc_init(float acc[8][8], const float* __restrict__ bias, int d0) {
    float4 b0 = *(const float4*)(bias + d0);
    float4 b1 = *(const float4*)(bias + d0 + 4);
#pragma unroll
    for (int i = 0; i < 8; i++) {
        acc[i][0] = b0.x; acc[i][1] = b0.y; acc[i][2] = b0.z; acc[i][3] = b0.w;
        acc[i][4] = b1.x; acc[i][5] = b1.y; acc[i][6] = b1.z; acc[i][7] = b1.w;
    }
}

__device__ __forceinline__ void mm_acc(float acc[8][8], const float* __restrict__ WT,
                                       const float* __restrict__ A, int d0) {
#pragma unroll 2
    for (int k = 0; k < 128; k++) {
        float4 w0 = *(const float4*)(WT + k * DK + d0);
        float4 w1 = *(const float4*)(WT + k * DK + d0 + 4);
#pragma unroll
        for (int i = 0; i < 8; i++) {
            float av = A[i * DK + k];
            acc[i][0] = fmaf(av, w0.x, acc[i][0]);
            acc[i][1] = fmaf(av, w0.y, acc[i][1]);
            acc[i][2] = fmaf(av, w0.z, acc[i][2]);
            acc[i][3] = fmaf(av, w0.w, acc[i][3]);
            acc[i][4] = fmaf(av, w1.x, acc[i][4]);
            acc[i][5] = fmaf(av, w1.y, acc[i][5]);
            acc[i][6] = fmaf(av, w1.z, acc[i][6]);
            acc[i][7] = fmaf(av, w1.w, acc[i][7]);
        }
    }
}

__device__ __forceinline__ void acc_store(const float acc[8][8], float* __restrict__ dst,
                                          int b, int t0, int d0) {
#pragma unroll
    for (int i = 0; i < 8; i++) {
        float4 o0 = { acc[i][0], acc[i][1], acc[i][2], acc[i][3] };
        float4 o1 = { acc[i][4], acc[i][5], acc[i][6], acc[i][7] };
        float* p = dst + ((b * SS) + (t0 + i)) * DK + d0;
        *(float4*)p = o0;
        *(float4*)(p + 4) = o1;
    }
}

// ---------------- K_AL ----------------
__global__ void __launch_bounds__(256) k_al(const int* __restrict__ e_data,
                                            const int* __restrict__ a_data,
                                            const int* __restrict__ at_data,
                                            const float* __restrict__ e_w,
                                            const float* __restrict__ at_w,
                                            const float* __restrict__ b1) {
    extern __shared__ float sm[];
    float* sE  = sm;
    float* sAT = sm + 16384;
    __shared__ int s_ei[128];
    __shared__ int s_ai[128];
    __shared__ float s_a[128];

    int b = blockIdx.x, tid = threadIdx.x;
    if (tid < 128) {
        s_ei[tid] = e_data[b * SS + tid];
        s_ai[tid] = at_data[b * SS + tid];
        s_a[tid]  = (float)a_data[b * SS + tid];
    }
    __syncthreads();
    for (int idx = tid; idx < 16384; idx += 256) {
        int t = idx >> 7, k = idx & 127;
        sE[idx]  = e_w[s_ei[t] * DK + k];
        sAT[idx] = at_w[s_ai[t] * DK + k];
    }
    __syncthreads();

    int d0 = (tid & 15) * 8, t0 = (tid >> 4) * 8;
    float acc[8][8];
    acc_init(acc, b1, d0);
    mm_acc(acc, g_WT + W1aT * DK * DK, sE + t0 * DK, d0);
    mm_acc(acc, g_WT + W1bT * DK * DK, sAT + t0 * DK, d0);

    float4 r0 = *(const float4*)(g_r1 + d0);
    float4 r1v = *(const float4*)(g_r1 + d0 + 4);
#pragma unroll
    for (int i = 0; i < 8; i++) {
        float a = s_a[t0 + i];
        acc[i][0] += a * r0.x;  acc[i][1] += a * r0.y;
        acc[i][2] += a * r0.z;  acc[i][3] += a * r0.w;
        acc[i][4] += a * r1v.x; acc[i][5] += a * r1v.y;
        acc[i][6] += a * r1v.z; acc[i][7] += a * r1v.w;
    }
    acc_store(acc, g_AL, b, t0, d0);
}

// ---------------- K_P ----------------
__global__ void __launch_bounds__(256) k_p(const int* __restrict__ e_data,
                                           const int* __restrict__ it_data,
                                           const float* __restrict__ e_w,
                                           const float* __restrict__ it_w,
                                           const float* __restrict__ b2,
                                           const float* __restrict__ b3,
                                           const float* __restrict__ b4,
                                           const float* __restrict__ b5) {
    extern __shared__ float sm[];
    float* sAL = sm + 128;        // row -1 = zero pad
    float* sX  = sm + 16512;
    __shared__ int s_ii[128];

    int b = blockIdx.x, tid = threadIdx.x;
    if (tid < 128) { s_ii[tid] = it_data[b * SS + tid]; sm[tid] = 0.f; }
    __syncthreads();
    for (int idx = tid; idx < 16384; idx += 256) {
        sAL[idx] = g_AL[b * 16384 + idx];
        sX[idx]  = it_w[s_ii[idx >> 7] * DK + (idx & 127)];
    }
    __syncthreads();

    int d0 = (tid & 15) * 8, t0 = (tid >> 4) * 8;
    float acc[8][8];

    acc_init(acc, b2, d0);
    mm_acc(acc, g_WT + W2aT * DK * DK, sAL + (t0 - 1) * DK, d0);
    mm_acc(acc, g_WT + W2bT * DK * DK, sX + t0 * DK, d0);
    mm_acc(acc, g_WT + W2cT * DK * DK, sAL + t0 * DK, d0);
    acc_store(acc, g_P2, b, t0, d0);

    acc_init(acc, b3, d0);
    mm_acc(acc, g_WT + W3aT * DK * DK, sAL + (t0 - 1) * DK, d0);
    mm_acc(acc, g_WT + W3bT * DK * DK, sX + t0 * DK, d0);
    mm_acc(acc, g_WT + W3cT * DK * DK, sAL + t0 * DK, d0);
    acc_store(acc, g_P3, b, t0, d0);

    acc_init(acc, b4, d0);
    mm_acc(acc, g_WT + W4cT * DK * DK, sX + t0 * DK, d0);
    acc_store(acc, g_P4, b, t0, d0);

    __syncthreads();
    if (tid < 128) s_ii[tid] = (tid < 127) ? e_data[b * SS + tid + 1] : 0;
    __syncthreads();
    for (int idx = tid; idx < 16384; idx += 256) {
        int t = idx >> 7;
        sX[idx] = (t < 127) ? e_w[s_ii[t] * DK + (idx & 127)] : 0.f;
    }
    __syncthreads();

    acc_init(acc, b5, d0);
    mm_acc(acc, g_WT + W5aT * DK * DK, sX + t0 * DK, d0);
    acc_store(acc, g_P5, b, t0, d0);
}

// ---------------- main scan kernel ----------------
// SMEM byte layout (single extern char array):
//  Hs    [0, 81920)          fp32 H state, 128 rows x 160 (addr(n,k)=n*160+k+4*(n&7), floats)
//  Hsb   [81920, 118912)     bf16x2 H shadow, word(n,kw)=n*72+kw+4*(n&7), kw=k/2 in [0,64)
//  sWab  [118912, 151680)    W4a bf16x2, word = kt*1024 + d*8 + p  (p = within-tile k-word 0..7)
//  sW2   [151680, 184448)    W2d^T bf16x2, word = kw*128 + d   (k-pair packed)
//  sW3   [184448, 217216)    W3d^T bf16x2, same layout
//  small [217216, ...): ht(128f) LG(128f) cS(128f) arg(256f) qe(128f) qn(128f) htp(128f) red(16f)
#define HS_B    0
#define HSB_B   81920
#define SWAB_B  118912
#define SW2_B   151680
#define SW3_B   184448
#define HT_B    217216
#define LG_B    217728
#define CS_B    218240
#define ARG_B   218752
#define QE_B    219776
#define QN_B    220288
#define HTP_B   220800
#define RED_B   221312
#define SMEM_MAIN_BYTES 221376

__global__ void __launch_bounds__(256, 1) k_main(const int* __restrict__ e_data,
                                                 const float* __restrict__ qm,
                                                 const float* __restrict__ h0,
                                                 const float* __restrict__ W4,
                                                 float* __restrict__ out) {
    extern __shared__ char smc[];
    float*    Hs   = (float*)(smc + HS_B);
    uint32_t* Hsb  = (uint32_t*)(smc + HSB_B);
    uint32_t* sWab = (uint32_t*)(smc + SWAB_B);
    uint32_t* sW2  = (uint32_t*)(smc + SW2_B);
    uint32_t* sW3  = (uint32_t*)(smc + SW3_B);
    float*    ht   = (float*)(smc + HT_B);
    float*    LG   = (float*)(smc + LG_B);
    float*    cS   = (float*)(smc + CS_B);
    float*    arg  = (float*)(smc + ARG_B);
    float*    qe   = (float*)(smc + QE_B);
    float*    qn   = (float*)(smc + QN_B);
    float*    htp  = (float*)(smc + HTP_B);
    float*    red  = (float*)(smc + RED_B);

    const int b = blockIdx.x, tid = threadIdx.x;
    const int w = tid >> 5, l = tid & 31;
    const int u = l >> 2, r = l & 3;
    const int d0 = 16 * w + u;              // this thread's d rows: d0, d0+8

    const float* gW4bT = g_WT + W4bT * DK * DK;
    const float* gW5bT = g_WT + W5bT * DK * DK;

    // ---- SMEM init ----
    // W4a bf16 A-operand: word w_i -> d = w_i>>6, kw = w_i&63
    for (int w_i = tid; w_i < DK * 64; w_i += 256) {
        int d = w_i >> 6, kw = w_i & 63;
        float v0 = W4[d * 384 + 2 * kw];
        float v1 = W4[d * 384 + 2 * kw + 1];
        sWab[(kw >> 3) * 1024 + d * 8 + (kw & 7)] = pack_bf16(v0, v1);
    }
    // S1 weights bf16, k-pair packed: word = kw*128 + d
    for (int w_i = tid; w_i < 64 * DK; w_i += 256) {
        int kw = w_i >> 7, d = w_i & 127;
        sW2[w_i] = pack_bf16(g_WT[W2dT * DK * DK + (2 * kw) * DK + d],
                             g_WT[W2dT * DK * DK + (2 * kw + 1) * DK + d]);
        sW3[w_i] = pack_bf16(g_WT[W3dT * DK * DK + (2 * kw) * DK + d],
                             g_WT[W3dT * DK * DK + (2 * kw + 1) * DK + d]);
    }
    // H fp32 state + bf16 shadow
    for (int idx = tid; idx < DK * DK; idx += 256) {
        int n = idx >> 7, k = idx & 127;
        Hs[n * 160 + k + 4 * (n & 7)] = (n < NQ) ? h0[n * DK + k] : 0.f;
    }
    for (int w_i = tid; w_i < DK * 64; w_i += 256) {
        int n = w_i >> 6, kw = w_i & 63;
        float v0 = (n < NQ) ? h0[n * DK + 2 * kw] : 0.f;
        float v1 = (n < NQ) ? h0[n * DK + 2 * kw + 1] : 0.f;
        Hsb[n * 72 + 4 * (n & 7) + kw] = pack_bf16(v0, v1);
    }
    int eA = e_data[b * SS];          // qm row for qe at step t
    int eB = e_data[b * SS + 1];      // qm row for qn at step t
    if (tid < 128) {
        qe[tid] = (tid < NQ) ? qm[eA * NQ + tid] : 0.f;
        qn[tid] = 0.f;
    }
    __syncthreads();
    if (tid < 32) {
        float v = 0.f;
        for (int n = tid; n < NQ; n += 32) v += qe[n];
#pragma unroll
        for (int o = 16; o; o >>= 1) v += __shfl_xor_sync(0xffffffffu, v, o);
        if (tid == 0) red[0] = v;
    }
    __syncthreads();
    if (tid < 128) {
        float a = 0.f;
        for (int n = 0; n < NQ; n++) a += qe[n] * h0[n * DK + tid];
        ht[tid] = a / red[0];
    }
    if (tid == 0) out[b * SS] = 0.f;

    // ---- prefetch step-0 operands into registers ----
    float p_a, p4v = 0.f, p5v = 0.f, qv = 0.f, qnv = 0.f;
    {
        const int base = (b * SS) * DK;
        if (tid < 128) {
            p_a = g_P2[base + tid];
            p4v = g_P4[base + tid];
            p5v = g_P5[base + tid];
            qv  = (tid < NQ) ? qm[eA * NQ + tid] : 0.f;
        } else {
            p_a = g_P3[base + tid - 128];
            int m = tid - 128;
            qnv = (m < NQ) ? qm[eB * NQ + m] : 0.f;
        }
    }

    // per-thread B-frag base word: u*76 + r   (= u*72 + 4u + r, n=u<8)
    const int btw = u * 76 + r;
    // per-thread A-frag base within a kt block: d0*8 + r
    const int atb = d0 * 8 + r;
    // epilogue bf16-shadow store bases (byte offsets)
    const int hb0 = HSB_B + ((d0 >> 1) << 2) + ((d0 & 1) << 1) + 608 * r;

    // ---- scan ----
    for (int t = 0; t < SS - 1; t++) {
        __syncthreads();                        // sync1: Hs/Hsb/ht from prev step final
        if (tid < 128) qe[tid] = qv;
        else           qn[tid - 128] = qnv;

        // S4a FIRST: bf16 tensor GEMM  D'[d,n] = W4a . H^T  (acc in regs, kt dynamic)
        float acc[16][4];
#pragma unroll
        for (int nt = 0; nt < 16; nt++) { acc[nt][0] = 0.f; acc[nt][1] = 0.f; acc[nt][2] = 0.f; acc[nt][3] = 0.f; }
        for (int kt = 0; kt < 8; kt++) {
            const int ab = kt * 1024 + atb;
            uint32_t a4[4];
            a4[0] = sWab[ab];          // A[u][2r,2r+1]
            a4[1] = sWab[ab + 64];     // A[u+8][2r,2r+1]
            a4[2] = sWab[ab + 4];      // A[u][2r+8,2r+9]
            a4[3] = sWab[ab + 68];     // A[u+8][2r+8,2r+9]
            const uint32_t* Hk = Hsb + btw + kt * 8;
#pragma unroll
            for (int nt = 0; nt < 16; nt++) {
                uint32_t b0 = Hk[nt * 576];
                uint32_t b1 = Hk[nt * 576 + 4];
                mma16(acc[nt], a4, b0, b1);
            }
        }

        // S1: arg = P + W{2,3}d . ht   (bf16 smem weights, k-pair packed)
        {
            const uint32_t* WTb = (tid < 128) ? sW2 : sW3;
            int d = tid & 127;
            float a0 = p_a, a1 = 0.f, a2 = 0.f, a3 = 0.f;
#pragma unroll 8
            for (int kw = 0; kw < 64; kw += 2) {
                uint32_t w0 = WTb[kw * 128 + d];
                uint32_t w1 = WTb[(kw + 1) * 128 + d];
                float2 h0v = *(const float2*)(ht + 2 * kw);
                float2 h1v = *(const float2*)(ht + 2 * kw + 2);
                a0 = fmaf(h0v.x, bf_lo(w0), a0);
                a1 = fmaf(h0v.y, bf_hi(w0), a1);
                a2 = fmaf(h1v.x, bf_lo(w1), a2);
                a3 = fmaf(h1v.y, bf_hi(w1), a3);
            }
            arg[tid] = (a0 + a1) + (a2 + a3);
        }
        __syncthreads();                        // sync2: arg + qn ready

        // S2 (tid<128) || qn-sum (warp 4 lanes)
        if (tid < 128) {
            float lg = fast_tanh(arg[tid]);
            float gl = fast_sigmoid(arg[128 + tid]);
            LG[tid] = gl * (lg + 1.f) * 0.5f;
        } else if (tid < 160) {
            int lane = tid - 128;
            float v = 0.f;
            for (int n = lane; n < NQ; n += 32) v += qn[n];
#pragma unroll
            for (int o = 16; o; o >>= 1) v += __shfl_xor_sync(0xffffffffu, v, o);
            if (lane == 0) red[0] = v;
        }
        __syncthreads();                        // sync3: LG ready

        // S3: cS = P4 + LG @ W4b^T (split-k over 256 threads, fp32 global L2-hot)
        {
            int d = tid & 127, h = tid >> 7;
            const float* Wp = gW4bT + h * 64 * DK;
            const float* lgp = LG + h * 64;
            float a0 = h ? 0.f : p4v, a1 = 0.f, a2 = 0.f, a3 = 0.f;
#pragma unroll
            for (int k = 0; k < 64; k += 4) {
                a0 = fmaf(lgp[k + 0], Wp[(k + 0) * DK + d], a0);
                a1 = fmaf(lgp[k + 1], Wp[(k + 1) * DK + d], a1);
                a2 = fmaf(lgp[k + 2], Wp[(k + 2) * DK + d], a2);
                a3 = fmaf(lgp[k + 3], Wp[(k + 3) * DK + d], a3);
            }
            arg[tid] = (a0 + a1) + (a2 + a3);
        }
        __syncthreads();                        // sync4a
        if (tid < 128) cS[tid] = arg[tid] + arg[128 + tid];
        __syncthreads();                        // sync4b: cS ready; all MMA Hsb-reads retired

        // S4b epilogue: gamma=sigmoid(D+cS[d]); H <- qe[n]*LG[d] + gamma*H (fp32 + bf16 shadow);
        //               h_tilde partials
        {
            float cs0 = cS[d0], cs1 = cS[d0 + 8];
            float lg0 = LG[d0], lg1 = LG[d0 + 8];
            float s0 = 0.f, s1 = 0.f;
#pragma unroll
            for (int nt = 0; nt < 16; nt++) {
                int n0 = nt * 8 + 2 * r;
                float qe0 = qe[n0], qe1 = qe[n0 + 1];
                float qn0 = qn[n0], qn1 = qn[n0 + 1];
                float* p00 = &Hs[n0 * 160 + d0 + 8 * r];           // (n0,   d0)
                float* p01 = &Hs[(n0 + 1) * 160 + d0 + 8 * r + 4]; // (n0+1, d0)
                float h00 = p00[0], h10 = p00[8], h01 = p01[0], h11 = p01[8];
                float H00 = qe0 * lg0 + fast_sigmoid(acc[nt][0] + cs0) * h00;
                float H01 = qe1 * lg0 + fast_sigmoid(acc[nt][1] + cs0) * h01;
                float H10 = qe0 * lg1 + fast_sigmoid(acc[nt][2] + cs1) * h10;
                float H11 = qe1 * lg1 + fast_sigmoid(acc[nt][3] + cs1) * h11;
                p00[0] = H00; p01[0] = H01; p00[8] = H10; p01[8] = H11;
                // bf16 shadow stores (conflict-free; u-pairs merge into same word)
                int off00 = hb0 + nt * 2304;
                *(uint16_t*)(smc + off00)       = (uint16_t)pack_bf16(H00, 0.f);
                *(uint16_t*)(smc + off00 + 16)  = (uint16_t)pack_bf16(H10, 0.f);
                *(uint16_t*)(smc + off00 + 304) = (uint16_t)pack_bf16(H01, 0.f);
                *(uint16_t*)(smc + off00 + 320) = (uint16_t)pack_bf16(H11, 0.f);
                s0 = fmaf(qn0, H00, fmaf(qn1, H01, s0));
                s1 = fmaf(qn0, H10, fmaf(qn1, H11, s1));
            }
            s0 += __shfl_xor_sync(0xffffffffu, s0, 1);
            s0 += __shfl_xor_sync(0xffffffffu, s0, 2);
            s1 += __shfl_xor_sync(0xffffffffu, s1, 1);
            s1 += __shfl_xor_sync(0xffffffffu, s1, 2);
            if (r == 0) { htp[d0] = s0; htp[d0 + 8] = s1; }
        }
        __syncthreads();                        // sync5: htp + Hs/Hsb updated

        // h_tilde
        if (tid < 128) ht[tid] = htp[tid] / red[0];

        // ---- prefetch next step operands (overlaps S6 below) ----
        float p5cur = p5v;
        {
            int t2 = (t + 2 < SS) ? t + 2 : SS - 1;
            eA = eB;
            eB = e_data[b * SS + t2];
            const int base2 = (b * SS + t + 1) * DK;
            if (tid < 128) {
                p_a = g_P2[base2 + tid];
                p4v = g_P4[base2 + tid];
                p5v = g_P5[base2 + tid];
                qv  = (tid < NQ) ? qm[eA * NQ + tid] : 0.f;
            } else {
                p_a = g_P3[base2 + tid - 128];
                int m = tid - 128;
                qnv = (m < NQ) ? qm[eB * NQ + m] : 0.f;
            }
        }
        __syncthreads();                        // sync6: ht ready

        // S6: y = mean_d sigmoid(P5 + ht @ W5b^T) (split-k)
        {
            int d = tid & 127, h = tid >> 7;
            const float* Wp = gW5bT + h * 64 * DK;
            const float* hp = ht + h * 64;
            float a0 = h ? 0.f : p5cur, a1 = 0.f, a2 = 0.f, a3 = 0.f;
#pragma unroll
            for (int k = 0; k < 64; k += 4) {
                a0 = fmaf(hp[k + 0], Wp[(k + 0) * DK + d], a0);
                a1 = fmaf(hp[k + 1], Wp[(k + 1) * DK + d], a1);
                a2 = fmaf(hp[k + 2], Wp[(k + 2) * DK + d], a2);
                a3 = fmaf(hp[k + 3], Wp[(k + 3) * DK + d], a3);
            }
            arg[tid] = (a0 + a1) + (a2 + a3);
        }
        __syncthreads();                        // sync7
        float v = 0.f;
        if (tid < 128) v = fast_sigmoid(arg[tid] + arg[128 + tid]);
#pragma unroll
        for (int o = 16; o; o >>= 1) v += __shfl_xor_sync(0xffffffffu, v, o);
        if (tid < 128 && l == 0) red[8 + w] = v;
        __syncthreads();                        // sync8
        if (tid == 0)
            out[b * SS + t + 1] = (red[8] + red[9] + red[10] + red[11]) * (1.0f / 128.0f);
    }
}

// ---------------- host launcher ----------------
extern "C" void kernel_launch(void* const* d_in, const int* in_sizes, int n_in,
                              void* d_out, int out_size) {
    (void)in_sizes; (void)n_in; (void)out_size;
    const int*   e_data  = (const int*)d_in[0];
    const int*   a_data  = (const int*)d_in[1];
    const int*   it_data = (const int*)d_in[2];
    const int*   at_data = (const int*)d_in[3];
    const float* qm      = (const float*)d_in[4];
    const float* e_w     = (const float*)d_in[5];
    const float* at_w    = (const float*)d_in[6];
    const float* it_w    = (const float*)d_in[7];
    const float* h0      = (const float*)d_in[8];
    const float* W1      = (const float*)d_in[9];
    const float* b1      = (const float*)d_in[10];
    const float* W2      = (const float*)d_in[11];
    const float* b2      = (const float*)d_in[12];
    const float* W3      = (const float*)d_in[13];
    const float* b3      = (const float*)d_in[14];
    const float* W4      = (const float*)d_in[15];
    const float* b4      = (const float*)d_in[16];
    const float* W5      = (const float*)d_in[17];
    const float* b5      = (const float*)d_in[18];
    float* out = (float*)d_out;

    const int smem_al   = 2 * 128 * 128 * (int)sizeof(float);            // 131072
    const int smem_p    = (2 * 128 * 128 + 128) * (int)sizeof(float);    // 131584
    const int smem_main = SMEM_MAIN_BYTES;                               // 221376

    cudaFuncSetAttribute(k_al,   cudaFuncAttributeMaxDynamicSharedMemorySize, smem_al);
    cudaFuncSetAttribute(k_p,    cudaFuncAttributeMaxDynamicSharedMemorySize, smem_p);
    cudaFuncSetAttribute(k_main, cudaFuncAttributeMaxDynamicSharedMemorySize, smem_main);

    k_transpose<<<15, 256>>>(W1, W2, W3, W4, W5);
    k_al<<<BB, 256, smem_al>>>(e_data, a_data, at_data, e_w, at_w, b1);
    k_p<<<BB, 256, smem_p>>>(e_data, it_data, e_w, it_w, b2, b3, b4, b5);
    k_main<<<BB, 256, smem_main>>>(e_data, qm, h0, W4, out);
}

// round 13
// speedup vs baseline: 3.2470x; 1.1824x over previous
#include <cuda_runtime.h>
#include <cstdint>

#define DK 128
#define BB 128
#define SS 128
#define NQ 101

// ---------------- device-global scratch (no runtime allocation) ----------------
__device__ float g_AL[BB * SS * DK];   // all_learning
__device__ float g_P2[BB * SS * DK];   // precomputed z@W2 (non-recurrent part) + b2
__device__ float g_P3[BB * SS * DK];
__device__ float g_P4[BB * SS * DK];   // it@W4c^T + b4
__device__ float g_P5[BB * SS * DK];   // e_next@W5a^T + b5
__device__ float g_WT[15 * DK * DK];   // transposed 128x128 weight slices [k][d]
__device__ float g_r1[DK];             // rowsum of W1[:,256:384]

// WT slice ids
#define W1aT 0
#define W1bT 1
#define W2aT 2
#define W2bT 3
#define W2cT 4
#define W2dT 5
#define W3aT 6
#define W3bT 7
#define W3cT 8
#define W3dT 9
#define W4aT 10
#define W4bT 11
#define W4cT 12
#define W5aT 13
#define W5bT 14

__device__ __forceinline__ float fast_tanh(float x) {
    float y;
    asm("tanh.approx.f32 %0, %1;" : "=f"(y) : "f"(x));
    return y;
}
__device__ __forceinline__ float fast_sigmoid(float x) {
    return fmaf(fast_tanh(x * 0.5f), 0.5f, 0.5f);
}

// pack two fp32 into bf16x2 (lo = first arg, hi = second)
__device__ __forceinline__ uint32_t pack_bf16(float lo, float hi) {
    uint32_t r;
    asm("cvt.rn.bf16x2.f32 %0, %1, %2;" : "=r"(r) : "f"(hi), "f"(lo));
    return r;
}
__device__ __forceinline__ float bf_lo(uint32_t w) { return __uint_as_float(w << 16); }
__device__ __forceinline__ float bf_hi(uint32_t w) { return __uint_as_float(w & 0xFFFF0000u); }
__device__ __forceinline__ uint16_t bf16_of(float v) {
    return (uint16_t)pack_bf16(v, 0.f);
}

// bf16 mma m16n8k16: D += A(16x16 row) * B(16x8 col), fp32 acc
__device__ __forceinline__ void mma16(float* acc, const uint32_t* a, uint32_t b0, uint32_t b1) {
    asm volatile(
        "mma.sync.aligned.m16n8k16.row.col.f32.bf16.bf16.f32 "
        "{%0,%1,%2,%3}, {%4,%5,%6,%7}, {%8,%9}, {%0,%1,%2,%3};"
        : "+f"(acc[0]), "+f"(acc[1]), "+f"(acc[2]), "+f"(acc[3])
        : "r"(a[0]), "r"(a[1]), "r"(a[2]), "r"(a[3]), "r"(b0), "r"(b1));
}

// ---------------- transpose kernel: build WT slices + r1 ----------------
__global__ void k_transpose(const float* __restrict__ W1, const float* __restrict__ W2,
                            const float* __restrict__ W3, const float* __restrict__ W4,
                            const float* __restrict__ W5) {
    int m = blockIdx.x;
    const float* src; int ld, off;
    switch (m) {
        case 0:  src = W1; ld = 384; off = 0;   break;
        case 1:  src = W1; ld = 384; off = 128; break;
        case 2:  src = W2; ld = 512; off = 0;   break;
        case 3:  src = W2; ld = 512; off = 128; break;
        case 4:  src = W2; ld = 512; off = 256; break;
        case 5:  src = W2; ld = 512; off = 384; break;
        case 6:  src = W3; ld = 512; off = 0;   break;
        case 7:  src = W3; ld = 512; off = 128; break;
        case 8:  src = W3; ld = 512; off = 256; break;
        case 9:  src = W3; ld = 512; off = 384; break;
        case 10: src = W4; ld = 384; off = 0;   break;
        case 11: src = W4; ld = 384; off = 128; break;
        case 12: src = W4; ld = 384; off = 256; break;
        case 13: src = W5; ld = 256; off = 0;   break;
        default: src = W5; ld = 256; off = 128; break;
    }
    float* dst = g_WT + m * DK * DK;
    for (int idx = threadIdx.x; idx < DK * DK; idx += blockDim.x) {
        int d = idx >> 7, k = idx & 127;
        dst[k * DK + d] = src[d * ld + off + k];
    }
    if (m == 0) {
        for (int d = threadIdx.x; d < DK; d += blockDim.x) {
            float s = 0.f;
            for (int j = 0; j < 128; j++) s += W1[d * 384 + 256 + j];
            g_r1[d] = s;
        }
    }
}

// ---------------- GEMM helpers for prologue (8t x 8d register blocking) ----------------
__device__ __forceinline__ void acc_init(float acc[8][8], const float* __restrict__ bias, int d0) {
    float4 b0 = *(const float4*)(bias + d0);
    float4 b1 = *(const float4*)(bias + d0 + 4);
#pragma unroll
    for (int i = 0; i < 8; i++) {
        acc[i][0] = b0.x; acc[i][1] = b0.y; acc[i][2] = b0.z; acc[i][3] = b0.w;
        acc[i][4] = b1.x; acc[i][5] = b1.y; acc[i][6] = b1.z; acc[i][7] = b1.w;
    }
}

__device__ __forceinline__ void mm_acc(float acc[8][8], const float* __restrict__ WT,
                                       const float* __restrict__ A, int d0) {
#pragma unroll 2
    for (int k = 0; k < 128; k++) {
        float4 w0 = *(const float4*)(WT + k * DK + d0);
        float4 w1 = *(const float4*)(WT + k * DK + d0 + 4);
#pragma unroll
        for (int i = 0; i < 8; i++) {
            float av = A[i * DK + k];
            acc[i][0] = fmaf(av, w0.x, acc[i][0]);
            acc[i][1] = fmaf(av, w0.y, acc[i][1]);
            acc[i][2] = fmaf(av, w0.z, acc[i][2]);
            acc[i][3] = fmaf(av, w0.w, acc[i][3]);
            acc[i][4] = fmaf(av, w1.x, acc[i][4]);
            acc[i][5] = fmaf(av, w1.y, acc[i][5]);
            acc[i][6] = fmaf(av, w1.z, acc[i][6]);
            acc[i][7] = fmaf(av, w1.w, acc[i][7]);
        }
    }
}

__device__ __forceinline__ void acc_store(const float acc[8][8], float* __restrict__ dst,
                                          int b, int t0, int d0) {
#pragma unroll
    for (int i = 0; i < 8; i++) {
        float4 o0 = { acc[i][0], acc[i][1], acc[i][2], acc[i][3] };
        float4 o1 = { acc[i][4], acc[i][5], acc[i][6], acc[i][7] };
        float* p = dst + ((b * SS) + (t0 + i)) * DK + d0;
        *(float4*)p = o0;
        *(float4*)(p + 4) = o1;
    }
}

// ---------------- K_AL ----------------
__global__ void __launch_bounds__(256) k_al(const int* __restrict__ e_data,
                                            const int* __restrict__ a_data,
                                            const int* __restrict__ at_data,
                                            const float* __restrict__ e_w,
                                            const float* __restrict__ at_w,
                                            const float* __restrict__ b1) {
    extern __shared__ float sm[];
    float* sE  = sm;
    float* sAT = sm + 16384;
    __shared__ int s_ei[128];
    __shared__ int s_ai[128];
    __shared__ float s_a[128];

    int b = blockIdx.x, tid = threadIdx.x;
    if (tid < 128) {
        s_ei[tid] = e_data[b * SS + tid];
        s_ai[tid] = at_data[b * SS + tid];
        s_a[tid]  = (float)a_data[b * SS + tid];
    }
    __syncthreads();
    for (int idx = tid; idx < 16384; idx += 256) {
        int t = idx >> 7, k = idx & 127;
        sE[idx]  = e_w[s_ei[t] * DK + k];
        sAT[idx] = at_w[s_ai[t] * DK + k];
    }
    __syncthreads();

    int d0 = (tid & 15) * 8, t0 = (tid >> 4) * 8;
    float acc[8][8];
    acc_init(acc, b1, d0);
    mm_acc(acc, g_WT + W1aT * DK * DK, sE + t0 * DK, d0);
    mm_acc(acc, g_WT + W1bT * DK * DK, sAT + t0 * DK, d0);

    float4 r0 = *(const float4*)(g_r1 + d0);
    float4 r1v = *(const float4*)(g_r1 + d0 + 4);
#pragma unroll
    for (int i = 0; i < 8; i++) {
        float a = s_a[t0 + i];
        acc[i][0] += a * r0.x;  acc[i][1] += a * r0.y;
        acc[i][2] += a * r0.z;  acc[i][3] += a * r0.w;
        acc[i][4] += a * r1v.x; acc[i][5] += a * r1v.y;
        acc[i][6] += a * r1v.z; acc[i][7] += a * r1v.w;
    }
    acc_store(acc, g_AL, b, t0, d0);
}

// ---------------- K_P ----------------
__global__ void __launch_bounds__(256) k_p(const int* __restrict__ e_data,
                                           const int* __restrict__ it_data,
                                           const float* __restrict__ e_w,
                                           const float* __restrict__ it_w,
                                           const float* __restrict__ b2,
                                           const float* __restrict__ b3,
                                           const float* __restrict__ b4,
                                           const float* __restrict__ b5) {
    extern __shared__ float sm[];
    float* sAL = sm + 128;        // row -1 = zero pad
    float* sX  = sm + 16512;
    __shared__ int s_ii[128];

    int b = blockIdx.x, tid = threadIdx.x;
    if (tid < 128) { s_ii[tid] = it_data[b * SS + tid]; sm[tid] = 0.f; }
    __syncthreads();
    for (int idx = tid; idx < 16384; idx += 256) {
        sAL[idx] = g_AL[b * 16384 + idx];
        sX[idx]  = it_w[s_ii[idx >> 7] * DK + (idx & 127)];
    }
    __syncthreads();

    int d0 = (tid & 15) * 8, t0 = (tid >> 4) * 8;
    float acc[8][8];

    acc_init(acc, b2, d0);
    mm_acc(acc, g_WT + W2aT * DK * DK, sAL + (t0 - 1) * DK, d0);
    mm_acc(acc, g_WT + W2bT * DK * DK, sX + t0 * DK, d0);
    mm_acc(acc, g_WT + W2cT * DK * DK, sAL + t0 * DK, d0);
    acc_store(acc, g_P2, b, t0, d0);

    acc_init(acc, b3, d0);
    mm_acc(acc, g_WT + W3aT * DK * DK, sAL + (t0 - 1) * DK, d0);
    mm_acc(acc, g_WT + W3bT * DK * DK, sX + t0 * DK, d0);
    mm_acc(acc, g_WT + W3cT * DK * DK, sAL + t0 * DK, d0);
    acc_store(acc, g_P3, b, t0, d0);

    acc_init(acc, b4, d0);
    mm_acc(acc, g_WT + W4cT * DK * DK, sX + t0 * DK, d0);
    acc_store(acc, g_P4, b, t0, d0);

    __syncthreads();
    if (tid < 128) s_ii[tid] = (tid < 127) ? e_data[b * SS + tid + 1] : 0;
    __syncthreads();
    for (int idx = tid; idx < 16384; idx += 256) {
        int t = idx >> 7;
        sX[idx] = (t < 127) ? e_w[s_ii[t] * DK + (idx & 127)] : 0.f;
    }
    __syncthreads();

    acc_init(acc, b5, d0);
    mm_acc(acc, g_WT + W5aT * DK * DK, sX + t0 * DK, d0);
    acc_store(acc, g_P5, b, t0, d0);
}

// ---------------- main scan kernel ----------------
// SMEM byte layout (single extern char array):
//  Hsb   [0, 36992)          bf16x2 H shadow, word(n,kw)=n*72+kw+4*(n&7), kw=k/2 in [0,64)
//  sWab  [36992, 69760)      W4a bf16x2, word = kt*1024 + d*8 + p
//  sW2   [69760, 102528)     W2d^T bf16x2, word = kw*128 + d  (k-pair packed)
//  sW3   [102528, 135296)    W3d^T bf16x2
//  sW4b  [135296, 168064)    W4b^T bf16x2, word = kw*128 + d
//  sW5b  [168064, 200832)    W5b^T bf16x2
//  ht [200832] LG [201344] cS [201856] arg [202368] qe [203392] qn [203904]
//  htp [204416, 205440)  (2 halves x 128 floats)   red [205440]
#define HSB_B   0
#define SWAB_B  36992
#define SW2_B   69760
#define SW3_B   102528
#define SW4B_B  135296
#define SW5B_B  168064
#define HT_B    200832
#define LG_B    201344
#define CS_B    201856
#define ARG_B   202368
#define QE_B    203392
#define QN_B    203904
#define HTP_B   204416
#define RED_B   205440
#define SMEM_MAIN_BYTES 205504

__global__ void __launch_bounds__(256, 1) k_main(const int* __restrict__ e_data,
                                                 const float* __restrict__ qm,
                                                 const float* __restrict__ h0,
                                                 const float* __restrict__ W4,
                                                 float* __restrict__ out) {
    extern __shared__ char smc[];
    uint32_t* Hsb  = (uint32_t*)(smc + HSB_B);
    uint32_t* sWab = (uint32_t*)(smc + SWAB_B);
    uint32_t* sW2  = (uint32_t*)(smc + SW2_B);
    uint32_t* sW3  = (uint32_t*)(smc + SW3_B);
    uint32_t* sW4b = (uint32_t*)(smc + SW4B_B);
    uint32_t* sW5b = (uint32_t*)(smc + SW5B_B);
    float*    ht   = (float*)(smc + HT_B);
    float*    LG   = (float*)(smc + LG_B);
    float*    cS   = (float*)(smc + CS_B);
    float*    arg  = (float*)(smc + ARG_B);
    float*    qe   = (float*)(smc + QE_B);
    float*    qn   = (float*)(smc + QN_B);
    float*    htp  = (float*)(smc + HTP_B);
    float*    red  = (float*)(smc + RED_B);

    const int b = blockIdx.x, tid = threadIdx.x;
    const int w = tid >> 5, l = tid & 31;
    const int u = l >> 2, r = l & 3;
    const int g = w & 3;                 // d-group: d in [32g, 32g+32)
    const int h = w >> 2;                // n-half:  n in [64h, 64h+64)
    const int da = 32 * g + u;           // d rows: da, da+8 (tile0), da+16, da+24 (tile1)

    // ---- SMEM init ----
    for (int w_i = tid; w_i < DK * 64; w_i += 256) {
        int d = w_i >> 6, kw = w_i & 63;
        sWab[(kw >> 3) * 1024 + d * 8 + (kw & 7)] =
            pack_bf16(W4[d * 384 + 2 * kw], W4[d * 384 + 2 * kw + 1]);
    }
    for (int w_i = tid; w_i < 64 * DK; w_i += 256) {
        int kw = w_i >> 7, d = w_i & 127;
        sW2[w_i]  = pack_bf16(g_WT[W2dT * DK * DK + (2 * kw) * DK + d],
                              g_WT[W2dT * DK * DK + (2 * kw + 1) * DK + d]);
        sW3[w_i]  = pack_bf16(g_WT[W3dT * DK * DK + (2 * kw) * DK + d],
                              g_WT[W3dT * DK * DK + (2 * kw + 1) * DK + d]);
        sW4b[w_i] = pack_bf16(g_WT[W4bT * DK * DK + (2 * kw) * DK + d],
                              g_WT[W4bT * DK * DK + (2 * kw + 1) * DK + d]);
        sW5b[w_i] = pack_bf16(g_WT[W5bT * DK * DK + (2 * kw) * DK + d],
                              g_WT[W5bT * DK * DK + (2 * kw + 1) * DK + d]);
    }
    for (int w_i = tid; w_i < DK * 64; w_i += 256) {
        int n = w_i >> 6, kw = w_i & 63;
        float v0 = (n < NQ) ? h0[n * DK + 2 * kw] : 0.f;
        float v1 = (n < NQ) ? h0[n * DK + 2 * kw + 1] : 0.f;
        Hsb[n * 72 + 4 * (n & 7) + kw] = pack_bf16(v0, v1);
    }
    // H state in REGISTERS: Hreg[a][nt][c]  c: 0=(da+16a, n0) 1=(da+16a, n0+1) 2=(+8,n0) 3=(+8,n0+1)
    float Hreg[2][8][4];
#pragma unroll
    for (int a = 0; a < 2; a++)
#pragma unroll
        for (int nt = 0; nt < 8; nt++) {
            int n0 = 64 * h + 8 * nt + 2 * r;
            int dd = da + 16 * a;
            Hreg[a][nt][0] = (n0 < NQ)     ? h0[n0 * DK + dd]           : 0.f;
            Hreg[a][nt][1] = (n0 + 1 < NQ) ? h0[(n0 + 1) * DK + dd]     : 0.f;
            Hreg[a][nt][2] = (n0 < NQ)     ? h0[n0 * DK + dd + 8]       : 0.f;
            Hreg[a][nt][3] = (n0 + 1 < NQ) ? h0[(n0 + 1) * DK + dd + 8] : 0.f;
        }

    int eA = e_data[b * SS];
    int eB = e_data[b * SS + 1];
    if (tid < 128) {
        qe[tid] = (tid < NQ) ? qm[eA * NQ + tid] : 0.f;
        qn[tid] = 0.f;
    }
    __syncthreads();
    if (tid < 32) {
        float v = 0.f;
        for (int n = tid; n < NQ; n += 32) v += qe[n];
#pragma unroll
        for (int o = 16; o; o >>= 1) v += __shfl_xor_sync(0xffffffffu, v, o);
        if (tid == 0) red[0] = v;
    }
    __syncthreads();
    if (tid < 128) {
        float a = 0.f;
        for (int n = 0; n < NQ; n++) a += qe[n] * h0[n * DK + tid];
        ht[tid] = a / red[0];
    }
    if (tid == 0) out[b * SS] = 0.f;

    // ---- prefetch step-0 operands ----
    float p_a, p4v = 0.f, p5v = 0.f, qv = 0.f, qnv = 0.f;
    {
        const int base = (b * SS) * DK;
        if (tid < 128) {
            p_a = g_P2[base + tid];
            p4v = g_P4[base + tid];
            p5v = g_P5[base + tid];
            qv  = (tid < NQ) ? qm[eA * NQ + tid] : 0.f;
        } else {
            p_a = g_P3[base + tid - 128];
            int m = tid - 128;
            qnv = (m < NQ) ? qm[eB * NQ + m] : 0.f;
        }
    }

    const int btw = u * 76 + r;                         // B-frag base within an 8-row block
    const uint32_t* HsbH = Hsb + h * 4608;              // this warp's n-half
    // bf16 shadow store base component: db = 4*((32g+u)>>1) + 2*(u&1)
    const int db = 64 * g + 4 * (u >> 1) + 2 * (u & 1);

    // ---- scan ----
    for (int t = 0; t < SS - 1; t++) {
        __syncthreads();                        // sync1: Hsb/ht from prev step final
        if (tid < 128) qe[tid] = qv;
        else           qn[tid - 128] = qnv;

        // S4a: bf16 tensor GEMM, this warp: D'[32 d x 64 n]
        float acc[2][8][4];
#pragma unroll
        for (int a = 0; a < 2; a++)
#pragma unroll
            for (int nt = 0; nt < 8; nt++) {
                acc[a][nt][0] = 0.f; acc[a][nt][1] = 0.f;
                acc[a][nt][2] = 0.f; acc[a][nt][3] = 0.f;
            }
        for (int kt = 0; kt < 8; kt++) {
            uint32_t a4[2][4];
#pragma unroll
            for (int a = 0; a < 2; a++) {
                int ab = kt * 1024 + (da + 16 * a) * 8 + r;
                a4[a][0] = sWab[ab];
                a4[a][1] = sWab[ab + 64];
                a4[a][2] = sWab[ab + 4];
                a4[a][3] = sWab[ab + 68];
            }
            const uint32_t* Hk = HsbH + btw + kt * 8;
#pragma unroll
            for (int nt = 0; nt < 8; nt++) {
                uint32_t b0 = Hk[nt * 576];
                uint32_t b1 = Hk[nt * 576 + 4];
                mma16(acc[0][nt], a4[0], b0, b1);
                mma16(acc[1][nt], a4[1], b0, b1);
            }
        }

        // S1: arg = P + W{2,3}d . ht   (bf16 smem weights, float4 ht)
        {
            const uint32_t* WTb = (tid < 128) ? sW2 : sW3;
            int d = tid & 127;
            float a0 = p_a, a1 = 0.f, a2 = 0.f, a3 = 0.f;
#pragma unroll 8
            for (int j = 0; j < 32; j++) {
                uint32_t w0 = WTb[(2 * j) * 128 + d];
                uint32_t w1 = WTb[(2 * j + 1) * 128 + d];
                float4 hv = *(const float4*)(ht + 4 * j);
                a0 = fmaf(hv.x, bf_lo(w0), a0);
                a1 = fmaf(hv.y, bf_hi(w0), a1);
                a2 = fmaf(hv.z, bf_lo(w1), a2);
                a3 = fmaf(hv.w, bf_hi(w1), a3);
            }
            arg[tid] = (a0 + a1) + (a2 + a3);
        }
        __syncthreads();                        // sync2: arg + qn ready

        // S2 (tid<128) || qn-sum
        if (tid < 128) {
            float lg = fast_tanh(arg[tid]);
            float gl = fast_sigmoid(arg[128 + tid]);
            LG[tid] = gl * (lg + 1.f) * 0.5f;
        } else if (tid < 160) {
            int lane = tid - 128;
            float v = 0.f;
            for (int n = lane; n < NQ; n += 32) v += qn[n];
#pragma unroll
            for (int o = 16; o; o >>= 1) v += __shfl_xor_sync(0xffffffffu, v, o);
            if (lane == 0) red[0] = v;
        }
        __syncthreads();                        // sync3: LG ready

        // S3: cS = P4 + LG @ W4b^T (split-k, bf16 smem weights)
        {
            int d = tid & 127, hh = tid >> 7;
            const uint32_t* Wp = sW4b + hh * 32 * 128;
            const float* lgp = LG + hh * 64;
            float a0 = hh ? 0.f : p4v, a1 = 0.f, a2 = 0.f, a3 = 0.f;
#pragma unroll 8
            for (int kw = 0; kw < 32; kw += 2) {
                uint32_t w0 = Wp[kw * 128 + d];
                uint32_t w1 = Wp[(kw + 1) * 128 + d];
                float4 lv = *(const float4*)(lgp + 2 * kw);
                a0 = fmaf(lv.x, bf_lo(w0), a0);
                a1 = fmaf(lv.y, bf_hi(w0), a1);
                a2 = fmaf(lv.z, bf_lo(w1), a2);
                a3 = fmaf(lv.w, bf_hi(w1), a3);
            }
            arg[tid] = (a0 + a1) + (a2 + a3);
        }
        __syncthreads();                        // sync4a
        if (tid < 128) cS[tid] = arg[tid] + arg[128 + tid];
        __syncthreads();                        // sync4b: cS ready; all MMA Hsb-reads retired

        // S4b epilogue: gamma=sigmoid(D+cS); Hreg <- qe*LG + gamma*Hreg; bf16 shadow; h_tilde partials
        {
            float cs[2][2], lg[2][2];
#pragma unroll
            for (int a = 0; a < 2; a++) {
                cs[a][0] = cS[da + 16 * a];     cs[a][1] = cS[da + 16 * a + 8];
                lg[a][0] = LG[da + 16 * a];     lg[a][1] = LG[da + 16 * a + 8];
            }
            float s[2][2] = {{0.f, 0.f}, {0.f, 0.f}};
#pragma unroll
            for (int a = 0; a < 2; a++) {
#pragma unroll
                for (int nt = 0; nt < 8; nt++) {
                    int n0 = 64 * h + 8 * nt + 2 * r;
                    float2 qev = *(const float2*)(qe + n0);
                    float2 qnv2 = *(const float2*)(qn + n0);
                    float H00 = qev.x * lg[a][0] + fast_sigmoid(acc[a][nt][0] + cs[a][0]) * Hreg[a][nt][0];
                    float H01 = qev.y * lg[a][0] + fast_sigmoid(acc[a][nt][1] + cs[a][0]) * Hreg[a][nt][1];
                    float H10 = qev.x * lg[a][1] + fast_sigmoid(acc[a][nt][2] + cs[a][1]) * Hreg[a][nt][2];
                    float H11 = qev.y * lg[a][1] + fast_sigmoid(acc[a][nt][3] + cs[a][1]) * Hreg[a][nt][3];
                    Hreg[a][nt][0] = H00; Hreg[a][nt][1] = H01;
                    Hreg[a][nt][2] = H10; Hreg[a][nt][3] = H11;
                    int bn = HSB_B + 288 * n0 + 32 * r + db + 32 * a;
                    *(uint16_t*)(smc + bn)       = bf16_of(H00);
                    *(uint16_t*)(smc + bn + 16)  = bf16_of(H10);
                    *(uint16_t*)(smc + bn + 304) = bf16_of(H01);
                    *(uint16_t*)(smc + bn + 320) = bf16_of(H11);
                    s[a][0] = fmaf(qnv2.x, H00, fmaf(qnv2.y, H01, s[a][0]));
                    s[a][1] = fmaf(qnv2.x, H10, fmaf(qnv2.y, H11, s[a][1]));
                }
            }
#pragma unroll
            for (int a = 0; a < 2; a++) {
                s[a][0] += __shfl_xor_sync(0xffffffffu, s[a][0], 1);
                s[a][0] += __shfl_xor_sync(0xffffffffu, s[a][0], 2);
                s[a][1] += __shfl_xor_sync(0xffffffffu, s[a][1], 1);
                s[a][1] += __shfl_xor_sync(0xffffffffu, s[a][1], 2);
            }
            if (r == 0) {
                htp[h * 128 + da]      = s[0][0];
                htp[h * 128 + da + 8]  = s[0][1];
                htp[h * 128 + da + 16] = s[1][0];
                htp[h * 128 + da + 24] = s[1][1];
            }
        }
        __syncthreads();                        // sync5: htp + Hsb updated

        // h_tilde
        if (tid < 128) ht[tid] = (htp[tid] + htp[128 + tid]) / red[0];

        // ---- prefetch next step operands (overlaps S6) ----
        float p5cur = p5v;
        {
            int t2 = (t + 2 < SS) ? t + 2 : SS - 1;
            eA = eB;
            eB = e_data[b * SS + t2];
            const int base2 = (b * SS + t + 1) * DK;
            if (tid < 128) {
                p_a = g_P2[base2 + tid];
                p4v = g_P4[base2 + tid];
                p5v = g_P5[base2 + tid];
                qv  = (tid < NQ) ? qm[eA * NQ + tid] : 0.f;
            } else {
                p_a = g_P3[base2 + tid - 128];
                int m = tid - 128;
                qnv = (m < NQ) ? qm[eB * NQ + m] : 0.f;
            }
        }
        __syncthreads();                        // sync6: ht ready

        // S6: y = mean_d sigmoid(P5 + ht @ W5b^T) (split-k, bf16 smem weights)
        {
            int d = tid & 127, hh = tid >> 7;
            const uint32_t* Wp = sW5b + hh * 32 * 128;
            const float* hp = ht + hh * 64;
            float a0 = hh ? 0.f : p5cur, a1 = 0.f, a2 = 0.f, a3 = 0.f;
#pragma unroll 8
            for (int kw = 0; kw < 32; kw += 2) {
                uint32_t w0 = Wp[kw * 128 + d];
                uint32_t w1 = Wp[(kw + 1) * 128 + d];
                float4 hv = *(const float4*)(hp + 2 * kw);
                a0 = fmaf(hv.x, bf_lo(w0), a0);
                a1 = fmaf(hv.y, bf_hi(w0), a1);
                a2 = fmaf(hv.z, bf_lo(w1), a2);
                a3 = fmaf(hv.w, bf_hi(w1), a3);
            }
            arg[tid] = (a0 + a1) + (a2 + a3);
        }
        __syncthreads();                        // sync7
        float v = 0.f;
        if (tid < 128) v = fast_sigmoid(arg[tid] + arg[128 + tid]);
#pragma unroll
        for (int o = 16; o; o >>= 1) v += __shfl_xor_sync(0xffffffffu, v, o);
        if (tid < 128 && l == 0) red[8 + w] = v;
        __syncthreads();                        // sync8
        if (tid == 0)
            out[b * SS + t + 1] = (red[8] + red[9] + red[10] + red[11]) * (1.0f / 128.0f);
    }
}

// ---------------- host launcher ----------------
extern "C" void kernel_launch(void* const* d_in, const int* in_sizes, int n_in,
                              void* d_out, int out_size) {
    (void)in_sizes; (void)n_in; (void)out_size;
    const int*   e_data  = (const int*)d_in[0];
    const int*   a_data  = (const int*)d_in[1];
    const int*   it_data = (const int*)d_in[2];
    const int*   at_data = (const int*)d_in[3];
    const float* qm      = (const float*)d_in[4];
    const float* e_w     = (const float*)d_in[5];
    const float* at_w    = (const float*)d_in[6];
    const float* it_w    = (const float*)d_in[7];
    const float* h0      = (const float*)d_in[8];
    const float* W1      = (const float*)d_in[9];
    const float* b1      = (const float*)d_in[10];
    const float* W2      = (const float*)d_in[11];
    const float* b2      = (const float*)d_in[12];
    const float* W3      = (const float*)d_in[13];
    const float* b3      = (const float*)d_in[14];
    const float* W4      = (const float*)d_in[15];
    const float* b4      = (const float*)d_in[16];
    const float* W5      = (const float*)d_in[17];
    const float* b5      = (const float*)d_in[18];
    float* out = (float*)d_out;

    const int smem_al   = 2 * 128 * 128 * (int)sizeof(float);            // 131072
    const int smem_p    = (2 * 128 * 128 + 128) * (int)sizeof(float);    // 131584
    const int smem_main = SMEM_MAIN_BYTES;                               // 205504

    cudaFuncSetAttribute(k_al,   cudaFuncAttributeMaxDynamicSharedMemorySize, smem_al);
    cudaFuncSetAttribute(k_p,    cudaFuncAttributeMaxDynamicSharedMemorySize, smem_p);
    cudaFuncSetAttribute(k_main, cudaFuncAttributeMaxDynamicSharedMemorySize, smem_main);

    k_transpose<<<15, 256>>>(W1, W2, W3, W4, W5);
    k_al<<<BB, 256, smem_al>>>(e_data, a_data, at_data, e_w, at_w, b1);
    k_p<<<BB, 256, smem_p>>>(e_data, it_data, e_w, it_w, b2, b3, b4, b5);
    k_main<<<BB, 256, smem_main>>>(e_data, qm, h0, W4, out);
}

// round 14
// speedup vs baseline: 4.9665x; 1.5295x over previous
#include <cuda_runtime.h>
#include <cstdint>

#define DK 128
#define BB 128
#define SS 128
#define NQ 101

// ---------------- device-global scratch (no runtime allocation) ----------------
__device__ float g_P2[BB * SS * DK];
__device__ float g_P3[BB * SS * DK];
__device__ float g_P4[BB * SS * DK];
__device__ float g_P5[BB * SS * DK];
__device__ uint32_t g_Wab[11 * 8192];  // bf16x2 A-frag layout: kt*1024 + d*8 + (kw&7)
__device__ uint32_t g_Wkp[4 * 8192];   // bf16x2 k-pair layout: kw*128 + d
__device__ float g_r1[DK];             // rowsum of W1[:,256:384]

// g_Wab slice ids
#define SL_W1a 0
#define SL_W1b 1
#define SL_W2a 2
#define SL_W2b 3
#define SL_W2c 4
#define SL_W3a 5
#define SL_W3b 6
#define SL_W3c 7
#define SL_W4c 8
#define SL_W5a 9
#define SL_W4a 10
// g_Wkp slices: 0=W2d 1=W3d 2=W4b 3=W5b

__device__ __forceinline__ float fast_tanh(float x) {
    float y;
    asm("tanh.approx.f32 %0, %1;" : "=f"(y) : "f"(x));
    return y;
}
__device__ __forceinline__ float fast_sigmoid(float x) {
    return fmaf(fast_tanh(x * 0.5f), 0.5f, 0.5f);
}

__device__ __forceinline__ uint32_t pack_bf16(float lo, float hi) {
    uint32_t r;
    asm("cvt.rn.bf16x2.f32 %0, %1, %2;" : "=r"(r) : "f"(hi), "f"(lo));
    return r;
}
__device__ __forceinline__ float bf_lo(uint32_t w) { return __uint_as_float(w << 16); }
__device__ __forceinline__ float bf_hi(uint32_t w) { return __uint_as_float(w & 0xFFFF0000u); }
__device__ __forceinline__ uint16_t bf16_of(float v) { return (uint16_t)pack_bf16(v, 0.f); }

// bf16 mma m16n8k16: D += A(16x16 row) * B(16x8 col), fp32 acc
__device__ __forceinline__ void mma16(float* acc, const uint32_t* a, uint32_t b0, uint32_t b1) {
    asm volatile(
        "mma.sync.aligned.m16n8k16.row.col.f32.bf16.bf16.f32 "
        "{%0,%1,%2,%3}, {%4,%5,%6,%7}, {%8,%9}, {%0,%1,%2,%3};"
        : "+f"(acc[0]), "+f"(acc[1]), "+f"(acc[2]), "+f"(acc[3])
        : "r"(a[0]), "r"(a[1]), "r"(a[2]), "r"(a[3]), "r"(b0), "r"(b1));
}

// ---------------- k_transpose: build bf16 weight tables + r1 ----------------
__global__ void k_transpose(const float* __restrict__ W1, const float* __restrict__ W2,
                            const float* __restrict__ W3, const float* __restrict__ W4,
                            const float* __restrict__ W5) {
    int m = blockIdx.x, tid = threadIdx.x;
    const float* src; int ld, off;
    switch (m) {
        case 0:  src = W1; ld = 384; off = 0;   break;  // W1a
        case 1:  src = W1; ld = 384; off = 128; break;  // W1b
        case 2:  src = W2; ld = 512; off = 0;   break;  // W2a
        case 3:  src = W2; ld = 512; off = 128; break;  // W2b
        case 4:  src = W2; ld = 512; off = 256; break;  // W2c
        case 5:  src = W3; ld = 512; off = 0;   break;  // W3a
        case 6:  src = W3; ld = 512; off = 128; break;  // W3b
        case 7:  src = W3; ld = 512; off = 256; break;  // W3c
        case 8:  src = W4; ld = 384; off = 256; break;  // W4c
        case 9:  src = W5; ld = 256; off = 0;   break;  // W5a
        case 10: src = W4; ld = 384; off = 0;   break;  // W4a
        case 11: src = W2; ld = 512; off = 384; break;  // W2d
        case 12: src = W3; ld = 512; off = 384; break;  // W3d
        case 13: src = W4; ld = 384; off = 128; break;  // W4b
        default: src = W5; ld = 256; off = 128; break;  // W5b
    }
    if (m < 11) {
        uint32_t* dst = g_Wab + m * 8192;
        for (int i = tid; i < 8192; i += 256) {
            int d = i >> 6, kw = i & 63;
            dst[(kw >> 3) * 1024 + d * 8 + (kw & 7)] =
                pack_bf16(src[d * ld + off + 2 * kw], src[d * ld + off + 2 * kw + 1]);
        }
    } else {
        uint32_t* dst = g_Wkp + (m - 11) * 8192;
        for (int i = tid; i < 8192; i += 256) {
            int kw = i >> 7, d = i & 127;
            dst[i] = pack_bf16(src[d * ld + off + 2 * kw], src[d * ld + off + 2 * kw + 1]);
        }
    }
    if (m == 0) {
        for (int d = tid; d < DK; d += 256) {
            float s = 0.f;
            for (int j = 0; j < 128; j++) s += W1[d * 384 + 256 + j];
            g_r1[d] = s;
        }
    }
}

// ---------------- k_pre: AL + P2..P5 via bf16 tensor MMA ----------------
// smem words: sB0/1/2 = 131-row bf16x2 buffers (word(n,kw)=n*76+kw; row0 & 129/130 zero;
//             data rows 1..128), fp32 stage 128x132, idx/bias arrays.
#define PB_W    9956
#define PRE_SB0 0
#define PRE_SB1 9956
#define PRE_SB2 19912
#define PRE_STG 29868
#define PRE_EI  46764
#define PRE_AI  46892
#define PRE_II  47020
#define PRE_AF  47148
#define PRE_B1  47276
#define PRE_B2  47404
#define PRE_B3  47532
#define PRE_B4  47660
#define PRE_B5  47788
#define PRE_R1  47916
#define PRE_SMEM_BYTES (48044 * 4)

// one 128x128x128 GEMM pass: acc[d][t] += W . Y^T; rowoff selects Y time-shift
__device__ __forceinline__ void gemm_pass(float (&acc)[16][4], const uint32_t* __restrict__ gA,
                                          const uint32_t* sB, int rowoff, int dwu, int u, int r) {
    const uint32_t* Bb = sB + (u + rowoff) * 76 + r;
    for (int kt = 0; kt < 8; kt++) {
        uint32_t a4[4];
        int ai = kt * 1024 + dwu + r;
        a4[0] = gA[ai]; a4[1] = gA[ai + 64]; a4[2] = gA[ai + 4]; a4[3] = gA[ai + 68];
        const uint32_t* Bk = Bb + kt * 8;
#pragma unroll
        for (int nt = 0; nt < 16; nt++)
            mma16(acc[nt], a4, Bk[nt * 608], Bk[nt * 608 + 4]);
    }
}

__device__ __forceinline__ void acc_zero(float (&acc)[16][4]) {
#pragma unroll
    for (int nt = 0; nt < 16; nt++) {
        acc[nt][0] = 0.f; acc[nt][1] = 0.f; acc[nt][2] = 0.f; acc[nt][3] = 0.f;
    }
}

__device__ __forceinline__ void stage_epi(const float (&acc)[16][4], const float* bs,
                                          int d0, int r, float* stg) {
    float bb0 = bs[d0], bb1 = bs[d0 + 8];
#pragma unroll
    for (int nt = 0; nt < 16; nt++) {
        int t0 = 8 * nt + 2 * r;
        stg[t0 * 132 + d0]           = acc[nt][0] + bb0;
        stg[(t0 + 1) * 132 + d0]     = acc[nt][1] + bb0;
        stg[t0 * 132 + d0 + 8]       = acc[nt][2] + bb1;
        stg[(t0 + 1) * 132 + d0 + 8] = acc[nt][3] + bb1;
    }
}

__device__ __forceinline__ void copy_out(const float* stg, float* __restrict__ dst, int tid) {
#pragma unroll
    for (int j = 0; j < 16; j++) {
        int lin = (j * 256 + tid) * 4;
        int t = lin >> 7, d = lin & 127;
        float4 v = *(const float4*)(stg + t * 132 + d);
        *(float4*)(dst + lin) = v;
    }
}

__global__ void __launch_bounds__(256, 1) k_pre(const int* __restrict__ e_data,
                                                const int* __restrict__ a_data,
                                                const int* __restrict__ it_data,
                                                const int* __restrict__ at_data,
                                                const float* __restrict__ e_w,
                                                const float* __restrict__ at_w,
                                                const float* __restrict__ it_w,
                                                const float* __restrict__ b1,
                                                const float* __restrict__ b2,
                                                const float* __restrict__ b3,
                                                const float* __restrict__ b4,
                                                const float* __restrict__ b5) {
    extern __shared__ uint32_t ps[];
    uint32_t* sB0 = ps + PRE_SB0;
    uint32_t* sB1 = ps + PRE_SB1;
    uint32_t* sB2 = ps + PRE_SB2;
    float* stg  = (float*)(ps + PRE_STG);
    int*   s_ei = (int*)(ps + PRE_EI);
    int*   s_ai = (int*)(ps + PRE_AI);
    int*   s_ii = (int*)(ps + PRE_II);
    float* s_af = (float*)(ps + PRE_AF);
    float* b1s  = (float*)(ps + PRE_B1);
    float* b2s  = (float*)(ps + PRE_B2);
    float* b3s  = (float*)(ps + PRE_B3);
    float* b4s  = (float*)(ps + PRE_B4);
    float* b5s  = (float*)(ps + PRE_B5);
    float* r1s  = (float*)(ps + PRE_R1);

    const int b = blockIdx.x, tid = threadIdx.x;
    const int w = tid >> 5, l = tid & 31, u = l >> 2, r = l & 3;
    const int d0 = 16 * w + u;
    const int dwu = d0 * 8;

    if (tid < 128) {
        s_ei[tid] = e_data[b * SS + tid];
        s_ai[tid] = at_data[b * SS + tid];
        s_ii[tid] = it_data[b * SS + tid];
        s_af[tid] = (float)a_data[b * SS + tid];
        b1s[tid] = b1[tid]; b2s[tid] = b2[tid]; b3s[tid] = b3[tid];
        b4s[tid] = b4[tid]; b5s[tid] = b5[tid];
        r1s[tid] = g_r1[tid];
    }
    for (int i = tid; i < 3 * 76; i += 256) {
        int rr = i / 76, cc = i % 76;
        int wd = (rr == 0 ? 0 : (rr == 1 ? 129 : 130)) * 76 + cc;
        sB0[wd] = 0u; sB1[wd] = 0u; sB2[wd] = 0u;
    }
    __syncthreads();
    // gather embeddings into bf16 B-layout (rows 1..128)
    for (int i = tid; i < 8192; i += 256) {
        int n = i >> 6, kw = i & 63;
        int wd = (n + 1) * 76 + kw;
        float2 ev = *(const float2*)(e_w + s_ei[n] * DK + 2 * kw);
        float2 av = *(const float2*)(at_w + s_ai[n] * DK + 2 * kw);
        float2 iv = *(const float2*)(it_w + s_ii[n] * DK + 2 * kw);
        sB0[wd] = pack_bf16(ev.x, ev.y);
        sB1[wd] = pack_bf16(av.x, av.y);
        sB2[wd] = pack_bf16(iv.x, iv.y);
    }
    __syncthreads();

    float acc[16][4];
    // ---- AL = e@W1a^T + at@W1b^T (+ b1 + a*r1 in epilogue) ----
    acc_zero(acc);
    gemm_pass(acc, g_Wab + SL_W1a * 8192, sB0, 1, dwu, u, r);
    gemm_pass(acc, g_Wab + SL_W1b * 8192, sB1, 1, dwu, u, r);
    __syncthreads();   // all sB1 (at_emb) reads complete before overwrite with AL
    {
        float bb0 = b1s[d0], bb1 = b1s[d0 + 8];
        float rr0 = r1s[d0], rr1 = r1s[d0 + 8];
        char* base = (char*)sB1;
        int byc = 4 * (d0 >> 1) + 2 * (d0 & 1);
#pragma unroll
        for (int nt = 0; nt < 16; nt++) {
            int t0 = 8 * nt + 2 * r;
            float a0f = s_af[t0], a1f = s_af[t0 + 1];
            float v00 = acc[nt][0] + bb0 + a0f * rr0;
            float v01 = acc[nt][1] + bb0 + a1f * rr0;
            float v10 = acc[nt][2] + bb1 + a0f * rr1;
            float v11 = acc[nt][3] + bb1 + a1f * rr1;
            int by = (t0 + 1) * 304 + byc;
            *(uint16_t*)(base + by)        = bf16_of(v00);
            *(uint16_t*)(base + by + 304)  = bf16_of(v01);
            *(uint16_t*)(base + by + 16)   = bf16_of(v10);
            *(uint16_t*)(base + by + 320)  = bf16_of(v11);
        }
    }
    __syncthreads();

    // ---- P2 = AL_prev@W2a + it@W2b + AL@W2c + b2 ----
    acc_zero(acc);
    gemm_pass(acc, g_Wab + SL_W2a * 8192, sB1, 0, dwu, u, r);
    gemm_pass(acc, g_Wab + SL_W2b * 8192, sB2, 1, dwu, u, r);
    gemm_pass(acc, g_Wab + SL_W2c * 8192, sB1, 1, dwu, u, r);
    stage_epi(acc, b2s, d0, r, stg);
    __syncthreads();
    copy_out(stg, g_P2 + b * SS * DK, tid);
    __syncthreads();

    // ---- P3 ----
    acc_zero(acc);
    gemm_pass(acc, g_Wab + SL_W3a * 8192, sB1, 0, dwu, u, r);
    gemm_pass(acc, g_Wab + SL_W3b * 8192, sB2, 1, dwu, u, r);
    gemm_pass(acc, g_Wab + SL_W3c * 8192, sB1, 1, dwu, u, r);
    stage_epi(acc, b3s, d0, r, stg);
    __syncthreads();
    copy_out(stg, g_P3 + b * SS * DK, tid);
    __syncthreads();

    // ---- P4 = it@W4c^T + b4 ----
    acc_zero(acc);
    gemm_pass(acc, g_Wab + SL_W4c * 8192, sB2, 1, dwu, u, r);
    stage_epi(acc, b4s, d0, r, stg);
    __syncthreads();
    copy_out(stg, g_P4 + b * SS * DK, tid);
    __syncthreads();

    // ---- P5 = e_next@W5a^T + b5 ----
    acc_zero(acc);
    gemm_pass(acc, g_Wab + SL_W5a * 8192, sB0, 2, dwu, u, r);
    stage_epi(acc, b5s, d0, r, stg);
    __syncthreads();
    copy_out(stg, g_P5 + b * SS * DK, tid);
}

// ---------------- main scan kernel ----------------
// SMEM bytes:
//  Hsb   [0, 38912)          bf16x2 H shadow, word(n,kw)=n*76+kw  (stride-76, no aliasing)
//  sWab  [38912, 71680)      W4a bf16x2 A-frag
//  sW2   [71680, 104448)     W2d^T bf16x2 k-pair
//  sW3   [104448, 137216)
//  sW4b  [137216, 169984)
//  sW5b  [169984, 202752)
//  ht[202752] LG[203264] cS[203776] arg[204288,1024] qe[205312] qn[205824]
//  htp[206336,1024] red[207360]
#define HSB_B   0
#define SWAB_B  38912
#define SW2_B   71680
#define SW3_B   104448
#define SW4B_B  137216
#define SW5B_B  169984
#define HT_B    202752
#define LG_B    203264
#define CS_B    203776
#define ARG_B   204288
#define QE_B    205312
#define QN_B    205824
#define HTP_B   206336
#define RED_B   207360
#define SMEM_MAIN_BYTES 207424

__global__ void __launch_bounds__(256, 1) k_main(const int* __restrict__ e_data,
                                                 const float* __restrict__ qm,
                                                 const float* __restrict__ h0,
                                                 float* __restrict__ out) {
    extern __shared__ char smc[];
    uint32_t* Hsb  = (uint32_t*)(smc + HSB_B);
    uint32_t* sWab = (uint32_t*)(smc + SWAB_B);
    uint32_t* sW2  = (uint32_t*)(smc + SW2_B);
    uint32_t* sW3  = (uint32_t*)(smc + SW3_B);
    uint32_t* sW4b = (uint32_t*)(smc + SW4B_B);
    uint32_t* sW5b = (uint32_t*)(smc + SW5B_B);
    float*    ht   = (float*)(smc + HT_B);
    float*    LG   = (float*)(smc + LG_B);
    float*    cS   = (float*)(smc + CS_B);
    float*    arg  = (float*)(smc + ARG_B);
    float*    qe   = (float*)(smc + QE_B);
    float*    qn   = (float*)(smc + QN_B);
    float*    htp  = (float*)(smc + HTP_B);
    float*    red  = (float*)(smc + RED_B);

    const int b = blockIdx.x, tid = threadIdx.x;
    const int w = tid >> 5, l = tid & 31;
    const int u = l >> 2, r = l & 3;
    const int g = w & 3;                 // d-group
    const int h = w >> 2;                // n-half
    const int da = 32 * g + u;

    // ---- SMEM init: straight bf16 copies ----
    for (int i = tid; i < 8192; i += 256) {
        sWab[i] = g_Wab[SL_W4a * 8192 + i];
        sW2[i]  = g_Wkp[i];
        sW3[i]  = g_Wkp[8192 + i];
        sW4b[i] = g_Wkp[16384 + i];
        sW5b[i] = g_Wkp[24576 + i];
    }
    for (int i = tid; i < 8192; i += 256) {
        int n = i >> 6, kw = i & 63;
        float v0 = (n < NQ) ? h0[n * DK + 2 * kw] : 0.f;
        float v1 = (n < NQ) ? h0[n * DK + 2 * kw + 1] : 0.f;
        Hsb[n * 76 + kw] = pack_bf16(v0, v1);
    }
    float Hreg[2][8][4];
#pragma unroll
    for (int a = 0; a < 2; a++)
#pragma unroll
        for (int nt = 0; nt < 8; nt++) {
            int n0 = 64 * h + 8 * nt + 2 * r;
            int dd = da + 16 * a;
            Hreg[a][nt][0] = (n0 < NQ)     ? h0[n0 * DK + dd]           : 0.f;
            Hreg[a][nt][1] = (n0 + 1 < NQ) ? h0[(n0 + 1) * DK + dd]     : 0.f;
            Hreg[a][nt][2] = (n0 < NQ)     ? h0[n0 * DK + dd + 8]       : 0.f;
            Hreg[a][nt][3] = (n0 + 1 < NQ) ? h0[(n0 + 1) * DK + dd + 8] : 0.f;
        }

    int eA = e_data[b * SS];
    int eB = e_data[b * SS + 1];
    if (tid < 128) {
        qe[tid] = (tid < NQ) ? qm[eA * NQ + tid] : 0.f;
        qn[tid] = 0.f;
    }
    __syncthreads();
    if (tid < 32) {
        float v = 0.f;
        for (int n = tid; n < NQ; n += 32) v += qe[n];
#pragma unroll
        for (int o = 16; o; o >>= 1) v += __shfl_xor_sync(0xffffffffu, v, o);
        if (tid == 0) red[0] = v;
    }
    __syncthreads();
    if (tid < 128) {
        float a = 0.f;
        for (int n = 0; n < NQ; n++) a += qe[n] * h0[n * DK + tid];
        ht[tid] = a / red[0];
    }
    if (tid == 0) out[b * SS] = 0.f;

    // ---- prefetch step-0 operands ----
    float p_a, p4v = 0.f, p5v = 0.f, qv = 0.f, qnv = 0.f;
    {
        const int base = (b * SS) * DK;
        if (tid < 128) {
            p_a = g_P2[base + tid];
            p4v = g_P4[base + tid];
            p5v = g_P5[base + tid];
            qv  = (tid < NQ) ? qm[eA * NQ + tid] : 0.f;
        } else {
            p_a = g_P3[base + tid - 128];
            int m = tid - 128;
            qnv = (m < NQ) ? qm[eB * NQ + m] : 0.f;
        }
    }

    const int btw = u * 76 + r;
    const uint32_t* HsbH = Hsb + h * 4864;
    const int db = 64 * g + 4 * (u >> 1) + 2 * (u & 1);
    const int hb0 = 304 * (64 * h + 2 * r) + db;   // + 2432*nt + 32*a

    // ---- scan ----
    for (int t = 0; t < SS - 1; t++) {
        __syncthreads();                        // sync1
        if (tid < 128) qe[tid] = qv;
        else           qn[tid - 128] = qnv;

        // S4a: bf16 tensor GEMM, warp: D'[32 d x 64 n]
        float acc[2][8][4];
#pragma unroll
        for (int a = 0; a < 2; a++)
#pragma unroll
            for (int nt = 0; nt < 8; nt++) {
                acc[a][nt][0] = 0.f; acc[a][nt][1] = 0.f;
                acc[a][nt][2] = 0.f; acc[a][nt][3] = 0.f;
            }
        for (int kt = 0; kt < 8; kt++) {
            uint32_t a4[2][4];
#pragma unroll
            for (int a = 0; a < 2; a++) {
                int ab = kt * 1024 + (da + 16 * a) * 8 + r;
                a4[a][0] = sWab[ab];
                a4[a][1] = sWab[ab + 64];
                a4[a][2] = sWab[ab + 4];
                a4[a][3] = sWab[ab + 68];
            }
            const uint32_t* Hk = HsbH + btw + kt * 8;
#pragma unroll
            for (int nt = 0; nt < 8; nt++) {
                uint32_t b0 = Hk[nt * 608];
                uint32_t b1 = Hk[nt * 608 + 4];
                mma16(acc[0][nt], a4[0], b0, b1);
                mma16(acc[1][nt], a4[1], b0, b1);
            }
        }

        // S1: arg = P + W{2,3}d . ht
        {
            const uint32_t* WTb = (tid < 128) ? sW2 : sW3;
            int d = tid & 127;
            float a0 = p_a, a1 = 0.f, a2 = 0.f, a3 = 0.f;
#pragma unroll 8
            for (int j = 0; j < 32; j++) {
                uint32_t w0 = WTb[(2 * j) * 128 + d];
                uint32_t w1 = WTb[(2 * j + 1) * 128 + d];
                float4 hv = *(const float4*)(ht + 4 * j);
                a0 = fmaf(hv.x, bf_lo(w0), a0);
                a1 = fmaf(hv.y, bf_hi(w0), a1);
                a2 = fmaf(hv.z, bf_lo(w1), a2);
                a3 = fmaf(hv.w, bf_hi(w1), a3);
            }
            arg[tid] = (a0 + a1) + (a2 + a3);
        }
        __syncthreads();                        // sync2

        if (tid < 128) {
            float lg = fast_tanh(arg[tid]);
            float gl = fast_sigmoid(arg[128 + tid]);
            LG[tid] = gl * (lg + 1.f) * 0.5f;
        } else if (tid < 160) {
            int lane = tid - 128;
            float v = 0.f;
            for (int n = lane; n < NQ; n += 32) v += qn[n];
#pragma unroll
            for (int o = 16; o; o >>= 1) v += __shfl_xor_sync(0xffffffffu, v, o);
            if (lane == 0) red[0] = v;
        }
        __syncthreads();                        // sync3

        // S3: cS = P4 + LG @ W4b^T
        {
            int d = tid & 127, hh = tid >> 7;
            const uint32_t* Wp = sW4b + hh * 32 * 128;
            const float* lgp = LG + hh * 64;
            float a0 = hh ? 0.f : p4v, a1 = 0.f, a2 = 0.f, a3 = 0.f;
#pragma unroll 8
            for (int kw = 0; kw < 32; kw += 2) {
                uint32_t w0 = Wp[kw * 128 + d];
                uint32_t w1 = Wp[(kw + 1) * 128 + d];
                float4 lv = *(const float4*)(lgp + 2 * kw);
                a0 = fmaf(lv.x, bf_lo(w0), a0);
                a1 = fmaf(lv.y, bf_hi(w0), a1);
                a2 = fmaf(lv.z, bf_lo(w1), a2);
                a3 = fmaf(lv.w, bf_hi(w1), a3);
            }
            arg[tid] = (a0 + a1) + (a2 + a3);
        }
        __syncthreads();                        // sync4a
        if (tid < 128) cS[tid] = arg[tid] + arg[128 + tid];
        __syncthreads();                        // sync4b

        // S4b epilogue
        {
            float cs[2][2], lg[2][2];
#pragma unroll
            for (int a = 0; a < 2; a++) {
                cs[a][0] = cS[da + 16 * a];     cs[a][1] = cS[da + 16 * a + 8];
                lg[a][0] = LG[da + 16 * a];     lg[a][1] = LG[da + 16 * a + 8];
            }
            float s[2][2] = {{0.f, 0.f}, {0.f, 0.f}};
#pragma unroll
            for (int a = 0; a < 2; a++) {
#pragma unroll
                for (int nt = 0; nt < 8; nt++) {
                    int n0 = 64 * h + 8 * nt + 2 * r;
                    float2 qev = *(const float2*)(qe + n0);
                    float2 qnv2 = *(const float2*)(qn + n0);
                    float H00 = qev.x * lg[a][0] + fast_sigmoid(acc[a][nt][0] + cs[a][0]) * Hreg[a][nt][0];
                    float H01 = qev.y * lg[a][0] + fast_sigmoid(acc[a][nt][1] + cs[a][0]) * Hreg[a][nt][1];
                    float H10 = qev.x * lg[a][1] + fast_sigmoid(acc[a][nt][2] + cs[a][1]) * Hreg[a][nt][2];
                    float H11 = qev.y * lg[a][1] + fast_sigmoid(acc[a][nt][3] + cs[a][1]) * Hreg[a][nt][3];
                    Hreg[a][nt][0] = H00; Hreg[a][nt][1] = H01;
                    Hreg[a][nt][2] = H10; Hreg[a][nt][3] = H11;
                    int bn = hb0 + 2432 * nt + 32 * a;
                    *(uint16_t*)(smc + bn)       = bf16_of(H00);
                    *(uint16_t*)(smc + bn + 16)  = bf16_of(H10);
                    *(uint16_t*)(smc + bn + 304) = bf16_of(H01);
                    *(uint16_t*)(smc + bn + 320) = bf16_of(H11);
                    s[a][0] = fmaf(qnv2.x, H00, fmaf(qnv2.y, H01, s[a][0]));
                    s[a][1] = fmaf(qnv2.x, H10, fmaf(qnv2.y, H11, s[a][1]));
                }
            }
#pragma unroll
            for (int a = 0; a < 2; a++) {
                s[a][0] += __shfl_xor_sync(0xffffffffu, s[a][0], 1);
                s[a][0] += __shfl_xor_sync(0xffffffffu, s[a][0], 2);
                s[a][1] += __shfl_xor_sync(0xffffffffu, s[a][1], 1);
                s[a][1] += __shfl_xor_sync(0xffffffffu, s[a][1], 2);
            }
            if (r == 0) {
                htp[h * 128 + da]      = s[0][0];
                htp[h * 128 + da + 8]  = s[0][1];
                htp[h * 128 + da + 16] = s[1][0];
                htp[h * 128 + da + 24] = s[1][1];
            }
        }
        __syncthreads();                        // sync5

        if (tid < 128) ht[tid] = (htp[tid] + htp[128 + tid]) / red[0];

        // prefetch next step operands
        float p5cur = p5v;
        {
            int t2 = (t + 2 < SS) ? t + 2 : SS - 1;
            eA = eB;
            eB = e_data[b * SS + t2];
            const int base2 = (b * SS + t + 1) * DK;
            if (tid < 128) {
                p_a = g_P2[base2 + tid];
                p4v = g_P4[base2 + tid];
                p5v = g_P5[base2 + tid];
                qv  = (tid < NQ) ? qm[eA * NQ + tid] : 0.f;
            } else {
                p_a = g_P3[base2 + tid - 128];
                int m = tid - 128;
                qnv = (m < NQ) ? qm[eB * NQ + m] : 0.f;
            }
        }
        __syncthreads();                        // sync6

        // S6: y = mean_d sigmoid(P5 + ht @ W5b^T)
        {
            int d = tid & 127, hh = tid >> 7;
            const uint32_t* Wp = sW5b + hh * 32 * 128;
            const float* hp = ht + hh * 64;
            float a0 = hh ? 0.f : p5cur, a1 = 0.f, a2 = 0.f, a3 = 0.f;
#pragma unroll 8
            for (int kw = 0; kw < 32; kw += 2) {
                uint32_t w0 = Wp[kw * 128 + d];
                uint32_t w1 = Wp[(kw + 1) * 128 + d];
                float4 hv = *(const float4*)(hp + 2 * kw);
                a0 = fmaf(hv.x, bf_lo(w0), a0);
                a1 = fmaf(hv.y, bf_hi(w0), a1);
                a2 = fmaf(hv.z, bf_lo(w1), a2);
                a3 = fmaf(hv.w, bf_hi(w1), a3);
            }
            arg[tid] = (a0 + a1) + (a2 + a3);
        }
        __syncthreads();                        // sync7
        float v = 0.f;
        if (tid < 128) v = fast_sigmoid(arg[tid] + arg[128 + tid]);
#pragma unroll
        for (int o = 16; o; o >>= 1) v += __shfl_xor_sync(0xffffffffu, v, o);
        if (tid < 128 && l == 0) red[8 + w] = v;
        __syncthreads();                        // sync8
        if (tid == 0)
            out[b * SS + t + 1] = (red[8] + red[9] + red[10] + red[11]) * (1.0f / 128.0f);
    }
}

// ---------------- host launcher ----------------
extern "C" void kernel_launch(void* const* d_in, const int* in_sizes, int n_in,
                              void* d_out, int out_size) {
    (void)in_sizes; (void)n_in; (void)out_size;
    const int*   e_data  = (const int*)d_in[0];
    const int*   a_data  = (const int*)d_in[1];
    const int*   it_data = (const int*)d_in[2];
    const int*   at_data = (const int*)d_in[3];
    const float* qm      = (const float*)d_in[4];
    const float* e_w     = (const float*)d_in[5];
    const float* at_w    = (const float*)d_in[6];
    const float* it_w    = (const float*)d_in[7];
    const float* h0      = (const float*)d_in[8];
    const float* W1      = (const float*)d_in[9];
    const float* b1      = (const float*)d_in[10];
    const float* W2      = (const float*)d_in[11];
    const float* b2      = (const float*)d_in[12];
    const float* W3      = (const float*)d_in[13];
    const float* b3      = (const float*)d_in[14];
    const float* W4      = (const float*)d_in[15];
    const float* b4      = (const float*)d_in[16];
    const float* W5      = (const float*)d_in[17];
    const float* b5      = (const float*)d_in[18];
    float* out = (float*)d_out;

    cudaFuncSetAttribute(k_pre,  cudaFuncAttributeMaxDynamicSharedMemorySize, PRE_SMEM_BYTES);
    cudaFuncSetAttribute(k_main, cudaFuncAttributeMaxDynamicSharedMemorySize, SMEM_MAIN_BYTES);

    k_transpose<<<15, 256>>>(W1, W2, W3, W4, W5);
    k_pre<<<BB, 256, PRE_SMEM_BYTES>>>(e_data, a_data, it_data, at_data,
                                       e_w, at_w, it_w, b1, b2, b3, b4, b5);
    k_main<<<BB, 256, SMEM_MAIN_BYTES>>>(e_data, qm, h0, out);
    (void)W4;
}

// round 15
// speedup vs baseline: 5.2168x; 1.0504x over previous
#include <cuda_runtime.h>
#include <cstdint>

#define DK 128
#define BB 128
#define SS 128
#define NQ 101

// ---------------- device-global scratch (no runtime allocation) ----------------
__device__ float g_P2[BB * SS * DK];
__device__ float g_P3[BB * SS * DK];
__device__ float g_P4[BB * SS * DK];
__device__ float g_P5[BB * SS * DK];
__device__ uint32_t g_Wab[11 * 8192];  // bf16x2 A-frag layout: kt*1024 + d*8 + (kw&7)
__device__ uint32_t g_Wz[16384];       // W2d/W3d stacked 256-row A-frag: kt*2048 + dz*8 + (kw&7)
__device__ uint32_t g_Wkp[2 * 8192];   // bf16x2 k-pair layout: kw*128 + d  (0=W4b 1=W5b)
__device__ float g_r1[DK];             // rowsum of W1[:,256:384]

// g_Wab slice ids
#define SL_W1a 0
#define SL_W1b 1
#define SL_W2a 2
#define SL_W2b 3
#define SL_W2c 4
#define SL_W3a 5
#define SL_W3b 6
#define SL_W3c 7
#define SL_W4c 8
#define SL_W5a 9
#define SL_W4a 10

__device__ __forceinline__ float fast_tanh(float x) {
    float y;
    asm("tanh.approx.f32 %0, %1;" : "=f"(y) : "f"(x));
    return y;
}
__device__ __forceinline__ float fast_sigmoid(float x) {
    return fmaf(fast_tanh(x * 0.5f), 0.5f, 0.5f);
}

__device__ __forceinline__ uint32_t pack_bf16(float lo, float hi) {
    uint32_t r;
    asm("cvt.rn.bf16x2.f32 %0, %1, %2;" : "=r"(r) : "f"(hi), "f"(lo));
    return r;
}
__device__ __forceinline__ float bf_lo(uint32_t w) { return __uint_as_float(w << 16); }
__device__ __forceinline__ float bf_hi(uint32_t w) { return __uint_as_float(w & 0xFFFF0000u); }
__device__ __forceinline__ uint16_t bf16_of(float v) { return (uint16_t)pack_bf16(v, 0.f); }

// bf16 mma m16n8k16: D += A(16x16 row) * B(16x8 col), fp32 acc
__device__ __forceinline__ void mma16(float* acc, const uint32_t* a, uint32_t b0, uint32_t b1) {
    asm volatile(
        "mma.sync.aligned.m16n8k16.row.col.f32.bf16.bf16.f32 "
        "{%0,%1,%2,%3}, {%4,%5,%6,%7}, {%8,%9}, {%0,%1,%2,%3};"
        : "+f"(acc[0]), "+f"(acc[1]), "+f"(acc[2]), "+f"(acc[3])
        : "r"(a[0]), "r"(a[1]), "r"(a[2]), "r"(a[3]), "r"(b0), "r"(b1));
}

// ---------------- k_transpose: build bf16 weight tables + r1 ----------------
__global__ void k_transpose(const float* __restrict__ W1, const float* __restrict__ W2,
                            const float* __restrict__ W3, const float* __restrict__ W4,
                            const float* __restrict__ W5) {
    int m = blockIdx.x, tid = threadIdx.x;
    const float* src; int ld, off;
    switch (m) {
        case 0:  src = W1; ld = 384; off = 0;   break;  // W1a
        case 1:  src = W1; ld = 384; off = 128; break;  // W1b
        case 2:  src = W2; ld = 512; off = 0;   break;  // W2a
        case 3:  src = W2; ld = 512; off = 128; break;  // W2b
        case 4:  src = W2; ld = 512; off = 256; break;  // W2c
        case 5:  src = W3; ld = 512; off = 0;   break;  // W3a
        case 6:  src = W3; ld = 512; off = 128; break;  // W3b
        case 7:  src = W3; ld = 512; off = 256; break;  // W3c
        case 8:  src = W4; ld = 384; off = 256; break;  // W4c
        case 9:  src = W5; ld = 256; off = 0;   break;  // W5a
        case 10: src = W4; ld = 384; off = 0;   break;  // W4a
        case 11: src = W2; ld = 512; off = 384; break;  // W2d -> g_Wz rows 0..127
        case 12: src = W3; ld = 512; off = 384; break;  // W3d -> g_Wz rows 128..255
        case 13: src = W4; ld = 384; off = 128; break;  // W4b -> g_Wkp[0]
        default: src = W5; ld = 256; off = 128; break;  // W5b -> g_Wkp[1]
    }
    if (m < 11) {
        uint32_t* dst = g_Wab + m * 8192;
        for (int i = tid; i < 8192; i += 256) {
            int d = i >> 6, kw = i & 63;
            dst[(kw >> 3) * 1024 + d * 8 + (kw & 7)] =
                pack_bf16(src[d * ld + off + 2 * kw], src[d * ld + off + 2 * kw + 1]);
        }
    } else if (m < 13) {
        for (int i = tid; i < 8192; i += 256) {
            int d = i >> 6, kw = i & 63;
            int dz = d + (m - 11) * 128;
            g_Wz[(kw >> 3) * 2048 + dz * 8 + (kw & 7)] =
                pack_bf16(src[d * ld + off + 2 * kw], src[d * ld + off + 2 * kw + 1]);
        }
    } else {
        uint32_t* dst = g_Wkp + (m - 13) * 8192;
        for (int i = tid; i < 8192; i += 256) {
            int kw = i >> 7, d = i & 127;
            dst[i] = pack_bf16(src[d * ld + off + 2 * kw], src[d * ld + off + 2 * kw + 1]);
        }
    }
    if (m == 0) {
        for (int d = tid; d < DK; d += 256) {
            float s = 0.f;
            for (int j = 0; j < 128; j++) s += W1[d * 384 + 256 + j];
            g_r1[d] = s;
        }
    }
}

// ---------------- k_pre: AL + P2..P5 via bf16 tensor MMA ----------------
#define PB_W    9956
#define PRE_SB0 0
#define PRE_SB1 9956
#define PRE_SB2 19912
#define PRE_STG 29868
#define PRE_EI  46764
#define PRE_AI  46892
#define PRE_II  47020
#define PRE_AF  47148
#define PRE_B1  47276
#define PRE_B2  47404
#define PRE_B3  47532
#define PRE_B4  47660
#define PRE_B5  47788
#define PRE_R1  47916
#define PRE_SMEM_BYTES (48044 * 4)

__device__ __forceinline__ void gemm_pass(float (&acc)[16][4], const uint32_t* __restrict__ gA,
                                          const uint32_t* sB, int rowoff, int dwu, int u, int r) {
    const uint32_t* Bb = sB + (u + rowoff) * 76 + r;
    for (int kt = 0; kt < 8; kt++) {
        uint32_t a4[4];
        int ai = kt * 1024 + dwu + r;
        a4[0] = gA[ai]; a4[1] = gA[ai + 64]; a4[2] = gA[ai + 4]; a4[3] = gA[ai + 68];
        const uint32_t* Bk = Bb + kt * 8;
#pragma unroll
        for (int nt = 0; nt < 16; nt++)
            mma16(acc[nt], a4, Bk[nt * 608], Bk[nt * 608 + 4]);
    }
}

__device__ __forceinline__ void acc_zero16(float (&acc)[16][4]) {
#pragma unroll
    for (int nt = 0; nt < 16; nt++) {
        acc[nt][0] = 0.f; acc[nt][1] = 0.f; acc[nt][2] = 0.f; acc[nt][3] = 0.f;
    }
}

__device__ __forceinline__ void stage_epi(const float (&acc)[16][4], const float* bs,
                                          int d0, int r, float* stg) {
    float bb0 = bs[d0], bb1 = bs[d0 + 8];
#pragma unroll
    for (int nt = 0; nt < 16; nt++) {
        int t0 = 8 * nt + 2 * r;
        stg[t0 * 132 + d0]           = acc[nt][0] + bb0;
        stg[(t0 + 1) * 132 + d0]     = acc[nt][1] + bb0;
        stg[t0 * 132 + d0 + 8]       = acc[nt][2] + bb1;
        stg[(t0 + 1) * 132 + d0 + 8] = acc[nt][3] + bb1;
    }
}

__device__ __forceinline__ void copy_out(const float* stg, float* __restrict__ dst, int tid) {
#pragma unroll
    for (int j = 0; j < 16; j++) {
        int lin = (j * 256 + tid) * 4;
        int t = lin >> 7, d = lin & 127;
        float4 v = *(const float4*)(stg + t * 132 + d);
        *(float4*)(dst + lin) = v;
    }
}

__global__ void __launch_bounds__(256, 1) k_pre(const int* __restrict__ e_data,
                                                const int* __restrict__ a_data,
                                                const int* __restrict__ it_data,
                                                const int* __restrict__ at_data,
                                                const float* __restrict__ e_w,
                                                const float* __restrict__ at_w,
                                                const float* __restrict__ it_w,
                                                const float* __restrict__ b1,
                                                const float* __restrict__ b2,
                                                const float* __restrict__ b3,
                                                const float* __restrict__ b4,
                                                const float* __restrict__ b5) {
    extern __shared__ uint32_t ps[];
    uint32_t* sB0 = ps + PRE_SB0;
    uint32_t* sB1 = ps + PRE_SB1;
    uint32_t* sB2 = ps + PRE_SB2;
    float* stg  = (float*)(ps + PRE_STG);
    int*   s_ei = (int*)(ps + PRE_EI);
    int*   s_ai = (int*)(ps + PRE_AI);
    int*   s_ii = (int*)(ps + PRE_II);
    float* s_af = (float*)(ps + PRE_AF);
    float* b1s  = (float*)(ps + PRE_B1);
    float* b2s  = (float*)(ps + PRE_B2);
    float* b3s  = (float*)(ps + PRE_B3);
    float* b4s  = (float*)(ps + PRE_B4);
    float* b5s  = (float*)(ps + PRE_B5);
    float* r1s  = (float*)(ps + PRE_R1);

    const int b = blockIdx.x, tid = threadIdx.x;
    const int w = tid >> 5, l = tid & 31, u = l >> 2, r = l & 3;
    const int d0 = 16 * w + u;
    const int dwu = d0 * 8;

    if (tid < 128) {
        s_ei[tid] = e_data[b * SS + tid];
        s_ai[tid] = at_data[b * SS + tid];
        s_ii[tid] = it_data[b * SS + tid];
        s_af[tid] = (float)a_data[b * SS + tid];
        b1s[tid] = b1[tid]; b2s[tid] = b2[tid]; b3s[tid] = b3[tid];
        b4s[tid] = b4[tid]; b5s[tid] = b5[tid];
        r1s[tid] = g_r1[tid];
    }
    for (int i = tid; i < 3 * 76; i += 256) {
        int rr = i / 76, cc = i % 76;
        int wd = (rr == 0 ? 0 : (rr == 1 ? 129 : 130)) * 76 + cc;
        sB0[wd] = 0u; sB1[wd] = 0u; sB2[wd] = 0u;
    }
    __syncthreads();
    for (int i = tid; i < 8192; i += 256) {
        int n = i >> 6, kw = i & 63;
        int wd = (n + 1) * 76 + kw;
        float2 ev = *(const float2*)(e_w + s_ei[n] * DK + 2 * kw);
        float2 av = *(const float2*)(at_w + s_ai[n] * DK + 2 * kw);
        float2 iv = *(const float2*)(it_w + s_ii[n] * DK + 2 * kw);
        sB0[wd] = pack_bf16(ev.x, ev.y);
        sB1[wd] = pack_bf16(av.x, av.y);
        sB2[wd] = pack_bf16(iv.x, iv.y);
    }
    __syncthreads();

    float acc[16][4];
    acc_zero16(acc);
    gemm_pass(acc, g_Wab + SL_W1a * 8192, sB0, 1, dwu, u, r);
    gemm_pass(acc, g_Wab + SL_W1b * 8192, sB1, 1, dwu, u, r);
    __syncthreads();
    {
        float bb0 = b1s[d0], bb1 = b1s[d0 + 8];
        float rr0 = r1s[d0], rr1 = r1s[d0 + 8];
        char* base = (char*)sB1;
        int byc = 4 * (d0 >> 1) + 2 * (d0 & 1);
#pragma unroll
        for (int nt = 0; nt < 16; nt++) {
            int t0 = 8 * nt + 2 * r;
            float a0f = s_af[t0], a1f = s_af[t0 + 1];
            float v00 = acc[nt][0] + bb0 + a0f * rr0;
            float v01 = acc[nt][1] + bb0 + a1f * rr0;
            float v10 = acc[nt][2] + bb1 + a0f * rr1;
            float v11 = acc[nt][3] + bb1 + a1f * rr1;
            int by = (t0 + 1) * 304 + byc;
            *(uint16_t*)(base + by)        = bf16_of(v00);
            *(uint16_t*)(base + by + 304)  = bf16_of(v01);
            *(uint16_t*)(base + by + 16)   = bf16_of(v10);
            *(uint16_t*)(base + by + 320)  = bf16_of(v11);
        }
    }
    __syncthreads();

    acc_zero16(acc);
    gemm_pass(acc, g_Wab + SL_W2a * 8192, sB1, 0, dwu, u, r);
    gemm_pass(acc, g_Wab + SL_W2b * 8192, sB2, 1, dwu, u, r);
    gemm_pass(acc, g_Wab + SL_W2c * 8192, sB1, 1, dwu, u, r);
    stage_epi(acc, b2s, d0, r, stg);
    __syncthreads();
    copy_out(stg, g_P2 + b * SS * DK, tid);
    __syncthreads();

    acc_zero16(acc);
    gemm_pass(acc, g_Wab + SL_W3a * 8192, sB1, 0, dwu, u, r);
    gemm_pass(acc, g_Wab + SL_W3b * 8192, sB2, 1, dwu, u, r);
    gemm_pass(acc, g_Wab + SL_W3c * 8192, sB1, 1, dwu, u, r);
    stage_epi(acc, b3s, d0, r, stg);
    __syncthreads();
    copy_out(stg, g_P3 + b * SS * DK, tid);
    __syncthreads();

    acc_zero16(acc);
    gemm_pass(acc, g_Wab + SL_W4c * 8192, sB2, 1, dwu, u, r);
    stage_epi(acc, b4s, d0, r, stg);
    __syncthreads();
    copy_out(stg, g_P4 + b * SS * DK, tid);
    __syncthreads();

    acc_zero16(acc);
    gemm_pass(acc, g_Wab + SL_W5a * 8192, sB0, 2, dwu, u, r);
    stage_epi(acc, b5s, d0, r, stg);
    __syncthreads();
    copy_out(stg, g_P5 + b * SS * DK, tid);
}

// ---------------- main scan kernel ----------------
// SMEM bytes:
//  Hsb   [0, 38912)          bf16x2 H shadow, word(n,kw)=n*76+kw
//  sWab  [38912, 71680)      W4a A-frag
//  sWz   [71680, 137216)     W2d/W3d stacked 256-row A-frag (64KB)
//  sW4b  [137216, 169984)    k-pair
//  sW5b  [169984, 202752)    k-pair
//  ht[202752] LG[203264] htb[203776,256) pA3[204032,512) arg[204544,1024)
//  qe[205568] qn[206080] htp[206592,1024) red[207616,64)
#define HSB_B   0
#define SWAB_B  38912
#define SWZ_B   71680
#define SW4B_B  137216
#define SW5B_B  169984
#define HT_B    202752
#define LG_B    203264
#define HTB_B   203776
#define PA3_B   204032
#define ARG_B   204544
#define QE_B    205568
#define QN_B    206080
#define HTP_B   206592
#define RED_B   207616
#define SMEM_MAIN_BYTES 207680

template<int NT>
__device__ __forceinline__ void s4a_mma(float (&acc)[2][8][4], const uint32_t* sWab,
                                        const uint32_t* HsbH, int da, int r, int btw) {
    for (int kt = 0; kt < 8; kt++) {
        uint32_t a4[2][4];
#pragma unroll
        for (int a = 0; a < 2; a++) {
            int ab = kt * 1024 + (da + 16 * a) * 8 + r;
            a4[a][0] = sWab[ab];
            a4[a][1] = sWab[ab + 64];
            a4[a][2] = sWab[ab + 4];
            a4[a][3] = sWab[ab + 68];
        }
        const uint32_t* Hk = HsbH + btw + kt * 8;
#pragma unroll
        for (int nt = 0; nt < NT; nt++) {
            uint32_t b0 = Hk[nt * 608];
            uint32_t b1 = Hk[nt * 608 + 4];
            mma16(acc[0][nt], a4[0], b0, b1);
            mma16(acc[1][nt], a4[1], b0, b1);
        }
    }
}

template<int NT>
__device__ __forceinline__ void epi_step(float (&acc)[2][8][4], float (&Hreg)[2][8][4],
                                         const float* arg, const float* LG,
                                         const float* qe, const float* qn,
                                         char* smc, float* htp,
                                         int da, int h, int r, int hb0) {
    float cs[2][2], lg[2][2];
#pragma unroll
    for (int a = 0; a < 2; a++) {
        cs[a][0] = arg[da + 16 * a] + arg[128 + da + 16 * a];
        cs[a][1] = arg[da + 16 * a + 8] + arg[128 + da + 16 * a + 8];
        lg[a][0] = LG[da + 16 * a];
        lg[a][1] = LG[da + 16 * a + 8];
    }
    float s[2][2] = {{0.f, 0.f}, {0.f, 0.f}};
#pragma unroll
    for (int a = 0; a < 2; a++) {
#pragma unroll
        for (int nt = 0; nt < NT; nt++) {
            int n0 = 64 * h + 8 * nt + 2 * r;
            float2 qev = *(const float2*)(qe + n0);
            float2 qnv2 = *(const float2*)(qn + n0);
            float H00 = qev.x * lg[a][0] + fast_sigmoid(acc[a][nt][0] + cs[a][0]) * Hreg[a][nt][0];
            float H01 = qev.y * lg[a][0] + fast_sigmoid(acc[a][nt][1] + cs[a][0]) * Hreg[a][nt][1];
            float H10 = qev.x * lg[a][1] + fast_sigmoid(acc[a][nt][2] + cs[a][1]) * Hreg[a][nt][2];
            float H11 = qev.y * lg[a][1] + fast_sigmoid(acc[a][nt][3] + cs[a][1]) * Hreg[a][nt][3];
            Hreg[a][nt][0] = H00; Hreg[a][nt][1] = H01;
            Hreg[a][nt][2] = H10; Hreg[a][nt][3] = H11;
            int bn = hb0 + 2432 * nt + 32 * a;
            *(uint16_t*)(smc + bn)       = bf16_of(H00);
            *(uint16_t*)(smc + bn + 16)  = bf16_of(H10);
            *(uint16_t*)(smc + bn + 304) = bf16_of(H01);
            *(uint16_t*)(smc + bn + 320) = bf16_of(H11);
            s[a][0] = fmaf(qnv2.x, H00, fmaf(qnv2.y, H01, s[a][0]));
            s[a][1] = fmaf(qnv2.x, H10, fmaf(qnv2.y, H11, s[a][1]));
        }
    }
#pragma unroll
    for (int a = 0; a < 2; a++) {
        s[a][0] += __shfl_xor_sync(0xffffffffu, s[a][0], 1);
        s[a][0] += __shfl_xor_sync(0xffffffffu, s[a][0], 2);
        s[a][1] += __shfl_xor_sync(0xffffffffu, s[a][1], 1);
        s[a][1] += __shfl_xor_sync(0xffffffffu, s[a][1], 2);
    }
    if (r == 0) {
        htp[h * 128 + da]      = s[0][0];
        htp[h * 128 + da + 8]  = s[0][1];
        htp[h * 128 + da + 16] = s[1][0];
        htp[h * 128 + da + 24] = s[1][1];
    }
}

__global__ void __launch_bounds__(256, 1) k_main(const int* __restrict__ e_data,
                                                 const float* __restrict__ qm,
                                                 const float* __restrict__ h0,
                                                 float* __restrict__ out) {
    extern __shared__ char smc[];
    uint32_t* Hsb  = (uint32_t*)(smc + HSB_B);
    uint32_t* sWab = (uint32_t*)(smc + SWAB_B);
    uint32_t* sWz  = (uint32_t*)(smc + SWZ_B);
    uint32_t* sW4b = (uint32_t*)(smc + SW4B_B);
    uint32_t* sW5b = (uint32_t*)(smc + SW5B_B);
    float*    ht   = (float*)(smc + HT_B);
    float*    LG   = (float*)(smc + LG_B);
    uint32_t* htb  = (uint32_t*)(smc + HTB_B);
    float*    pA3  = (float*)(smc + PA3_B);
    float*    arg  = (float*)(smc + ARG_B);
    float*    qe   = (float*)(smc + QE_B);
    float*    qn   = (float*)(smc + QN_B);
    float*    htp  = (float*)(smc + HTP_B);
    float*    red  = (float*)(smc + RED_B);

    const int b = blockIdx.x, tid = threadIdx.x;
    const int w = tid >> 5, l = tid & 31;
    const int u = l >> 2, r = l & 3;
    const int g = w & 3;
    const int h = w >> 2;
    const int da = 32 * g + u;

    // ---- SMEM init ----
    for (int i = tid; i < 8192; i += 256) {
        sWab[i] = g_Wab[SL_W4a * 8192 + i];
        sW4b[i] = g_Wkp[i];
        sW5b[i] = g_Wkp[8192 + i];
    }
    for (int i = tid; i < 16384; i += 256) sWz[i] = g_Wz[i];
    for (int i = tid; i < 8192; i += 256) {
        int n = i >> 6, kw = i & 63;
        float v0 = (n < NQ) ? h0[n * DK + 2 * kw] : 0.f;
        float v1 = (n < NQ) ? h0[n * DK + 2 * kw + 1] : 0.f;
        Hsb[n * 76 + kw] = pack_bf16(v0, v1);
    }
    float Hreg[2][8][4];
#pragma unroll
    for (int a = 0; a < 2; a++)
#pragma unroll
        for (int nt = 0; nt < 8; nt++) {
            int n0 = 64 * h + 8 * nt + 2 * r;
            int dd = da + 16 * a;
            Hreg[a][nt][0] = (n0 < NQ)     ? h0[n0 * DK + dd]           : 0.f;
            Hreg[a][nt][1] = (n0 + 1 < NQ) ? h0[(n0 + 1) * DK + dd]     : 0.f;
            Hreg[a][nt][2] = (n0 < NQ)     ? h0[n0 * DK + dd + 8]       : 0.f;
            Hreg[a][nt][3] = (n0 + 1 < NQ) ? h0[(n0 + 1) * DK + dd + 8] : 0.f;
        }

    int eA = e_data[b * SS];
    int eB = e_data[b * SS + 1];
    if (tid < 128) {
        qe[tid] = (tid < NQ) ? qm[eA * NQ + tid] : 0.f;
        qn[tid] = 0.f;
    }
    __syncthreads();
    if (tid < 32) {
        float v = 0.f;
        for (int n = tid; n < NQ; n += 32) v += qe[n];
#pragma unroll
        for (int o = 16; o; o >>= 1) v += __shfl_xor_sync(0xffffffffu, v, o);
        if (tid == 0) red[0] = v;
    }
    __syncthreads();
    if (tid < 128) {
        float a = 0.f;
        for (int n = 0; n < NQ; n++) a += qe[n] * h0[n * DK + tid];
        ht[tid] = a / red[0];
    }
    if (tid == 0) out[b * SS] = 0.f;
    __syncthreads();
    if (tid < 64) htb[tid] = pack_bf16(ht[2 * tid], ht[2 * tid + 1]);

    // ---- prefetch step-0 operands ----
    float p_a, p4v = 0.f, p5v = 0.f, qv = 0.f, qnv = 0.f;
    {
        const int base = (b * SS) * DK;
        if (tid < 128) {
            p_a = g_P2[base + tid];
            p4v = g_P4[base + tid];
            p5v = g_P5[base + tid];
            qv  = (tid < NQ) ? qm[eA * NQ + tid] : 0.f;
        } else {
            p_a = g_P3[base + tid - 128];
            int m = tid - 128;
            qnv = (m < NQ) ? qm[eB * NQ + m] : 0.f;
        }
    }

    const int btw = u * 76 + r;
    const uint32_t* HsbH = Hsb + h * 4864;
    const int db = 64 * g + 4 * (u >> 1) + 2 * (u & 1);
    const int hb0 = 304 * (64 * h + 2 * r) + db;
    const int zb = 256 * w + 8 * u + r;        // S1-MMA A-frag base (dz=32w+u)

    // ---- scan ----
    for (int t = 0; t < SS - 1; t++) {
        __syncthreads();                        // sync1
        if (tid < 128) qe[tid] = qv;
        else { qn[tid - 128] = qnv; pA3[tid - 128] = p_a; }
        if (tid == 0 && t > 0)
            out[b * SS + t] = (red[8] + red[9] + red[10] + red[11]) * (1.0f / 128.0f);

        // S1-MMA: arg[0..255] = Wz . ht   (bf16 ht column in u==0 lanes)
        {
            float z0[4] = {0.f, 0.f, 0.f, 0.f};
            float z1[4] = {0.f, 0.f, 0.f, 0.f};
            for (int kt = 0; kt < 8; kt++) {
                const uint32_t* Wk = sWz + kt * 2048;
                uint32_t az0[4], az1[4];
                az0[0] = Wk[zb];        az0[1] = Wk[zb + 64];
                az0[2] = Wk[zb + 4];    az0[3] = Wk[zb + 68];
                az1[0] = Wk[zb + 128];  az1[1] = Wk[zb + 192];
                az1[2] = Wk[zb + 132];  az1[3] = Wk[zb + 196];
                uint32_t hb_0 = (u == 0) ? htb[kt * 8 + r] : 0u;
                uint32_t hb_1 = (u == 0) ? htb[kt * 8 + r + 4] : 0u;
                mma16(z0, az0, hb_0, hb_1);
                mma16(z1, az1, hb_0, hb_1);
            }
            if (r == 0) {
                arg[32 * w + u]      = z0[0];
                arg[32 * w + u + 8]  = z0[2];
                arg[32 * w + 16 + u] = z1[0];
                arg[32 * w + 24 + u] = z1[2];
            }
        }

        // S4a: bf16 tensor GEMM (N-trimmed: h=1 warps do 5 tiles)
        float acc[2][8][4];
#pragma unroll
        for (int a = 0; a < 2; a++)
#pragma unroll
            for (int nt = 0; nt < 8; nt++) {
                acc[a][nt][0] = 0.f; acc[a][nt][1] = 0.f;
                acc[a][nt][2] = 0.f; acc[a][nt][3] = 0.f;
            }
        if (h == 0) s4a_mma<8>(acc, sWab, HsbH, da, r, btw);
        else        s4a_mma<5>(acc, sWab, HsbH, da, r, btw);
        __syncthreads();                        // sync2

        // S2 (tid<128): LG from arg + own P2 / pA3  || qn-sum
        if (tid < 128) {
            float lg = fast_tanh(arg[tid] + p_a);
            float gl = fast_sigmoid(arg[128 + tid] + pA3[tid]);
            LG[tid] = gl * (lg + 1.f) * 0.5f;
        } else if (tid < 160) {
            int lane = tid - 128;
            float v = 0.f;
            for (int n = lane; n < NQ; n += 32) v += qn[n];
#pragma unroll
            for (int o = 16; o; o >>= 1) v += __shfl_xor_sync(0xffffffffu, v, o);
            if (lane == 0) red[0] = v;
        }
        __syncthreads();                        // sync3

        // S3: arg = (split-k halves of) P4 + LG @ W4b^T
        {
            int d = tid & 127, hh = tid >> 7;
            const uint32_t* Wp = sW4b + hh * 32 * 128;
            const float* lgp = LG + hh * 64;
            float a0 = hh ? 0.f : p4v, a1 = 0.f, a2 = 0.f, a3 = 0.f;
#pragma unroll 8
            for (int kw = 0; kw < 32; kw += 2) {
                uint32_t w0 = Wp[kw * 128 + d];
                uint32_t w1 = Wp[(kw + 1) * 128 + d];
                float4 lv = *(const float4*)(lgp + 2 * kw);
                a0 = fmaf(lv.x, bf_lo(w0), a0);
                a1 = fmaf(lv.y, bf_hi(w0), a1);
                a2 = fmaf(lv.z, bf_lo(w1), a2);
                a3 = fmaf(lv.w, bf_hi(w1), a3);
            }
            arg[tid] = (a0 + a1) + (a2 + a3);
        }
        __syncthreads();                        // sync4

        // S4b epilogue (cS read directly from arg halves)
        if (h == 0) epi_step<8>(acc, Hreg, arg, LG, qe, qn, smc, htp, da, h, r, hb0);
        else        epi_step<5>(acc, Hreg, arg, LG, qe, qn, smc, htp, da, h, r, hb0);
        __syncthreads();                        // sync5

        if (tid < 128) ht[tid] = (htp[tid] + htp[128 + tid]) / red[0];

        // prefetch next step operands
        float p5cur = p5v;
        {
            int t2 = (t + 2 < SS) ? t + 2 : SS - 1;
            eA = eB;
            eB = e_data[b * SS + t2];
            const int base2 = (b * SS + t + 1) * DK;
            if (tid < 128) {
                p_a = g_P2[base2 + tid];
                p4v = g_P4[base2 + tid];
                p5v = g_P5[base2 + tid];
                qv  = (tid < NQ) ? qm[eA * NQ + tid] : 0.f;
            } else {
                p_a = g_P3[base2 + tid - 128];
                int m = tid - 128;
                qnv = (m < NQ) ? qm[eB * NQ + m] : 0.f;
            }
        }
        __syncthreads();                        // sync6

        if (tid < 64) htb[tid] = pack_bf16(ht[2 * tid], ht[2 * tid + 1]);

        // S6: y = mean_d sigmoid(P5 + ht @ W5b^T)
        {
            int d = tid & 127, hh = tid >> 7;
            const uint32_t* Wp = sW5b + hh * 32 * 128;
            const float* hp = ht + hh * 64;
            float a0 = hh ? 0.f : p5cur, a1 = 0.f, a2 = 0.f, a3 = 0.f;
#pragma unroll 8
            for (int kw = 0; kw < 32; kw += 2) {
                uint32_t w0 = Wp[kw * 128 + d];
                uint32_t w1 = Wp[(kw + 1) * 128 + d];
                float4 hv = *(const float4*)(hp + 2 * kw);
                a0 = fmaf(hv.x, bf_lo(w0), a0);
                a1 = fmaf(hv.y, bf_hi(w0), a1);
                a2 = fmaf(hv.z, bf_lo(w1), a2);
                a3 = fmaf(hv.w, bf_hi(w1), a3);
            }
            arg[tid] = (a0 + a1) + (a2 + a3);
        }
        __syncthreads();                        // sync7
        float v = 0.f;
        if (tid < 128) v = fast_sigmoid(arg[tid] + arg[128 + tid]);
#pragma unroll
        for (int o = 16; o; o >>= 1) v += __shfl_xor_sync(0xffffffffu, v, o);
        if (tid < 128 && l == 0) red[8 + w] = v;
        // no sync8: out written after next sync1
    }
    __syncthreads();
    if (tid == 0)
        out[b * SS + SS - 1] = (red[8] + red[9] + red[10] + red[11]) * (1.0f / 128.0f);
}

// ---------------- host launcher ----------------
extern "C" void kernel_launch(void* const* d_in, const int* in_sizes, int n_in,
                              void* d_out, int out_size) {
    (void)in_sizes; (void)n_in; (void)out_size;
    const int*   e_data  = (const int*)d_in[0];
    const int*   a_data  = (const int*)d_in[1];
    const int*   it_data = (const int*)d_in[2];
    const int*   at_data = (const int*)d_in[3];
    const float* qm      = (const float*)d_in[4];
    const float* e_w     = (const float*)d_in[5];
    const float* at_w    = (const float*)d_in[6];
    const float* it_w    = (const float*)d_in[7];
    const float* h0      = (const float*)d_in[8];
    const float* W1      = (const float*)d_in[9];
    const float* b1      = (const float*)d_in[10];
    const float* W2      = (const float*)d_in[11];
    const float* b2      = (const float*)d_in[12];
    const float* W3      = (const float*)d_in[13];
    const float* b3      = (const float*)d_in[14];
    const float* W4      = (const float*)d_in[15];
    const float* b4      = (const float*)d_in[16];
    const float* W5      = (const float*)d_in[17];
    const float* b5      = (const float*)d_in[18];
    float* out = (float*)d_out;

    cudaFuncSetAttribute(k_pre,  cudaFuncAttributeMaxDynamicSharedMemorySize, PRE_SMEM_BYTES);
    cudaFuncSetAttribute(k_main, cudaFuncAttributeMaxDynamicSharedMemorySize, SMEM_MAIN_BYTES);

    k_transpose<<<15, 256>>>(W1, W2, W3, W4, W5);
    k_pre<<<BB, 256, PRE_SMEM_BYTES>>>(e_data, a_data, it_data, at_data,
                                       e_w, at_w, it_w, b1, b2, b3, b4, b5);
    k_main<<<BB, 256, SMEM_MAIN_BYTES>>>(e_data, qm, h0, out);
    (void)W4;
}